// round 8
// baseline (speedup 1.0000x reference)
#include <cuda_runtime.h>
#include <cuda_bf16.h>
#include <math_constants.h>
#include <cstdint>

#define N_TOTAL 32768
#define DIM     256
#define KCODES  1024
#define HW      1024
#define KP32    384            // 768 bf16 = 384 u32 pairs per row: [xhi | xlo | xhi]
#define MARGIN  4.0e-4f

// ---------------- scratch (16B-aligned: accessed via uint4) ----------------
__device__ __align__(16) uint32_t g_xpack[(size_t)N_TOTAL * KP32];   // 48MB packed A
__device__ __align__(16) uint32_t g_epack[(size_t)KCODES * KP32];    // 1.5MB packed B
__device__ float    g_rowsq[N_TOTAL];
__device__ float    g_embsq[KCODES];
__device__ int      g_idx[N_TOTAL];
__device__ unsigned short g_cand[N_TOTAL][16];
__device__ int      g_cnt[N_TOTAL];
__device__ double   g_partial[256];

// ---------------- prepack kernels ----------------
__global__ void k_pack_x(const float* __restrict__ x) {
    __shared__ float sT[32][129];
    int tid = threadIdx.x;
    int n0 = blockIdx.x * 128;
    int b = n0 >> 10, hw0 = n0 & 1023;
    const float* xb = x + (size_t)b * DIM * HW + hw0;
    for (int cc0 = 0; cc0 < DIM; cc0 += 32) {
        __syncthreads();
#pragma unroll
        for (int r = 0; r < 16; r++) {
            int idx = tid + r * 256;
            int ci = idx >> 7, nn = idx & 127;
            sT[ci][nn] = xb[(cc0 + ci) * HW + nn];
        }
        __syncthreads();
#pragma unroll
        for (int r = 0; r < 8; r++) {
            int idx = tid + r * 256;
            int nn = idx >> 4, cp = idx & 15;
            float f0 = sT[2 * cp][nn];
            float f1 = sT[2 * cp + 1][nn];
            __nv_bfloat16 h0 = __float2bfloat16_rn(f0);
            __nv_bfloat16 h1 = __float2bfloat16_rn(f1);
            __nv_bfloat16 l0 = __float2bfloat16_rn(__fsub_rn(f0, __bfloat162float(h0)));
            __nv_bfloat16 l1 = __float2bfloat16_rn(__fsub_rn(f1, __bfloat162float(h1)));
            uint32_t hp = ((uint32_t)__bfloat16_as_ushort(h1) << 16) | __bfloat16_as_ushort(h0);
            uint32_t lp = ((uint32_t)__bfloat16_as_ushort(l1) << 16) | __bfloat16_as_ushort(l0);
            uint32_t* row = g_xpack + (size_t)(n0 + nn) * KP32;
            int col = (cc0 >> 1) + cp;
            row[col]       = hp;   // xhi (pairs ehi)
            row[128 + col] = lp;   // xlo (pairs ehi)
            row[256 + col] = hp;   // xhi (pairs elo)
        }
    }
}

__global__ void k_pack_e(const float* __restrict__ e) {
    int id = blockIdx.x * blockDim.x + threadIdx.x;
    if (id >= KCODES * 128) return;
    int k = id >> 7, cp = id & 127;
    float f0 = e[(size_t)k * DIM + 2 * cp];
    float f1 = e[(size_t)k * DIM + 2 * cp + 1];
    __nv_bfloat16 h0 = __float2bfloat16_rn(f0);
    __nv_bfloat16 h1 = __float2bfloat16_rn(f1);
    __nv_bfloat16 l0 = __float2bfloat16_rn(__fsub_rn(f0, __bfloat162float(h0)));
    __nv_bfloat16 l1 = __float2bfloat16_rn(__fsub_rn(f1, __bfloat162float(h1)));
    uint32_t hp = ((uint32_t)__bfloat16_as_ushort(h1) << 16) | __bfloat16_as_ushort(h0);
    uint32_t lp = ((uint32_t)__bfloat16_as_ushort(l1) << 16) | __bfloat16_as_ushort(l0);
    uint32_t* row = g_epack + (size_t)k * KP32;
    row[cp]       = hp;  // ehi
    row[128 + cp] = hp;  // ehi
    row[256 + cp] = lp;  // elo
}

// ---------------- norms (exact, reference order) ----------------
__global__ void k_rowsq(const float* __restrict__ x) {
    int n = blockIdx.x * blockDim.x + threadIdx.x;
    if (n >= N_TOTAL) return;
    int b = n >> 10, hw = n & 1023;
    const float* p = x + (size_t)b * DIM * HW + hw;
    float acc = 0.f;
#pragma unroll 8
    for (int c = 0; c < DIM; c++) {
        float v = p[c * HW];
        acc = __fadd_rn(acc, __fmul_rn(v, v));
    }
    g_rowsq[n] = acc;
}

__global__ void k_embsq(const float* __restrict__ e) {
    int k = blockIdx.x * blockDim.x + threadIdx.x;
    if (k >= KCODES) return;
    const float* p = e + (size_t)k * DIM;
    float acc = 0.f;
#pragma unroll 8
    for (int c = 0; c < DIM; c++) {
        float v = p[c];
        acc = __fadd_rn(acc, __fmul_rn(v, v));
    }
    g_embsq[k] = acc;
}

// scalar zero: encodings region base is only 4B-aligned (out + 1 + 8388608)
__global__ void k_zero(float* __restrict__ p, long long count) {
    long long i = (long long)blockIdx.x * blockDim.x + threadIdx.x;
    if (i < count) p[i] = 0.0f;
}

// ---------------- HMMA GEMM + approx argmin + candidate capture ----------------
// Block: 128 rows x 1024 codes (8 panels of 128). 8 warps: wm in 0..3 (32-row
// tiles), wn in 0..1 (64-code tiles). mma m16n8k16 bf16 -> f32.
#define SA_STRIDE 388
#define SB_STRIDE 20
#define SB_OFF    (128 * SA_STRIDE)                 // 49664
#define SBK_OFF   (SB_OFF + 2 * 128 * SB_STRIDE)    // 54784
#define SCNT_OFF  (SBK_OFF + 1024)                  // 55808
#define SCAND_OFF (SCNT_OFF + 128)                  // 55936
#define SMEM_U32  (SCAND_OFF + 1024)                // sCand = 128*16 u16 = 1024 u32 (was 512: OOB!)
#define SMEM_BYTES (SMEM_U32 * 4)                   // 227840 B < 232448 B opt-in limit

__global__ __launch_bounds__(256, 1) void k_gemm() {
    extern __shared__ __align__(16) uint32_t sm[];
    uint32_t* sA = sm;
    uint32_t* sB = sm + SB_OFF;
    float*    sBk = (float*)(sm + SBK_OFF);
    int*      sCnt = (int*)(sm + SCNT_OFF);
    unsigned short* sCand = (unsigned short*)(sm + SCAND_OFF);

    int tid = threadIdx.x;
    int lane = tid & 31, w = tid >> 5;
    int g = lane >> 2, tg = lane & 3;
    int wm = w & 3, wn = w >> 2;
    int n0 = blockIdx.x * 128;

    for (int i = tid; i < KCODES; i += 256) sBk[i] = g_embsq[i];
    if (tid < 128) sCnt[tid] = 0;

    // ---- A panel -> SMEM (once) ----
    {
        const uint32_t* src = g_xpack + (size_t)n0 * KP32;
#pragma unroll
        for (int i = 0; i < 48; i++) {
            int idx = tid + i * 256;          // 0..12287 uint4s
            int row = idx / 96, q = idx - row * 96;
            uint4 v = *(const uint4*)(src + (size_t)row * KP32 + q * 4);
            *(uint4*)(sA + row * SA_STRIDE + q * 4) = v;
        }
    }
    __syncthreads();

    float runBest[4] = {CUDART_INF_F, CUDART_INF_F, CUDART_INF_F, CUDART_INF_F};
    uint4 pre[2];

    for (int p = 0; p < 8; p++) {
        float acc[2][8][4];
#pragma unroll
        for (int mt = 0; mt < 2; mt++)
#pragma unroll
            for (int nt = 0; nt < 8; nt++)
#pragma unroll
                for (int e2 = 0; e2 < 4; e2++) acc[mt][nt][e2] = 0.f;

        // prologue: chunk 0 -> buf 0
#pragma unroll
        for (int i = 0; i < 2; i++) {
            int idx = tid + i * 256;
            int code = idx >> 2, v = idx & 3;
            pre[i] = *(const uint4*)(g_epack + (size_t)(p * 128 + code) * KP32 + v * 4);
        }
#pragma unroll
        for (int i = 0; i < 2; i++) {
            int idx = tid + i * 256;
            int code = idx >> 2, v = idx & 3;
            *(uint4*)(sB + code * SB_STRIDE + v * 4) = pre[i];
        }
        __syncthreads();

        for (int c = 0; c < 24; c++) {
            int buf = c & 1;
            if (c < 23) {
                int cb = (c + 1) * 16;
#pragma unroll
                for (int i = 0; i < 2; i++) {
                    int idx = tid + i * 256;
                    int code = idx >> 2, v = idx & 3;
                    pre[i] = *(const uint4*)(g_epack + (size_t)(p * 128 + code) * KP32 + cb + v * 4);
                }
            }
            const uint32_t* Ab = sA + (wm * 32 + g) * SA_STRIDE + c * 16;
            const uint32_t* Bb = sB + buf * (128 * SB_STRIDE) + (wn * 64 + g) * SB_STRIDE;
#pragma unroll
            for (int ks = 0; ks < 2; ks++) {
                uint32_t a[2][4];
#pragma unroll
                for (int mt = 0; mt < 2; mt++) {
                    const uint32_t* ap = Ab + mt * 16 * SA_STRIDE + ks * 8 + tg;
                    a[mt][0] = ap[0];
                    a[mt][1] = ap[8 * SA_STRIDE];
                    a[mt][2] = ap[4];
                    a[mt][3] = ap[8 * SA_STRIDE + 4];
                }
#pragma unroll
                for (int nt = 0; nt < 8; nt++) {
                    uint32_t b0 = Bb[nt * 8 * SB_STRIDE + ks * 8 + tg];
                    uint32_t b1 = Bb[nt * 8 * SB_STRIDE + ks * 8 + tg + 4];
#pragma unroll
                    for (int mt = 0; mt < 2; mt++) {
                        asm volatile(
                            "mma.sync.aligned.m16n8k16.row.col.f32.bf16.bf16.f32 "
                            "{%0,%1,%2,%3}, {%4,%5,%6,%7}, {%8,%9}, {%0,%1,%2,%3};"
                            : "+f"(acc[mt][nt][0]), "+f"(acc[mt][nt][1]),
                              "+f"(acc[mt][nt][2]), "+f"(acc[mt][nt][3])
                            : "r"(a[mt][0]), "r"(a[mt][1]), "r"(a[mt][2]), "r"(a[mt][3]),
                              "r"(b0), "r"(b1));
                    }
                }
            }
            __syncthreads();
            if (c < 23) {
                int nb = buf ^ 1;
#pragma unroll
                for (int i = 0; i < 2; i++) {
                    int idx = tid + i * 256;
                    int code = idx >> 2, v = idx & 3;
                    *(uint4*)(sB + nb * (128 * SB_STRIDE) + code * SB_STRIDE + v * 4) = pre[i];
                }
                __syncthreads();
            }
        }

        // ---- panel epilogue: scores, per-row min, candidate capture ----
        int kbase = p * 128 + wn * 64 + 2 * tg;
        float bkv[8][2];
#pragma unroll
        for (int nt = 0; nt < 8; nt++) {
            bkv[nt][0] = sBk[kbase + nt * 8];
            bkv[nt][1] = sBk[kbase + nt * 8 + 1];
        }
        float mn[4] = {CUDART_INF_F, CUDART_INF_F, CUDART_INF_F, CUDART_INF_F};
#pragma unroll
        for (int mt = 0; mt < 2; mt++)
#pragma unroll
            for (int nt = 0; nt < 8; nt++) {
                float t0 = __fmaf_rn(-2.f, acc[mt][nt][0], bkv[nt][0]);
                float t1 = __fmaf_rn(-2.f, acc[mt][nt][1], bkv[nt][1]);
                float t2 = __fmaf_rn(-2.f, acc[mt][nt][2], bkv[nt][0]);
                float t3 = __fmaf_rn(-2.f, acc[mt][nt][3], bkv[nt][1]);
                mn[mt * 2]     = fminf(mn[mt * 2], fminf(t0, t1));
                mn[mt * 2 + 1] = fminf(mn[mt * 2 + 1], fminf(t2, t3));
            }
#pragma unroll
        for (int i = 0; i < 4; i++) {
            mn[i] = fminf(mn[i], __shfl_xor_sync(0xffffffffu, mn[i], 1));
            mn[i] = fminf(mn[i], __shfl_xor_sync(0xffffffffu, mn[i], 2));
            runBest[i] = fminf(runBest[i], mn[i]);
        }
#pragma unroll
        for (int mt = 0; mt < 2; mt++)
#pragma unroll
            for (int nt = 0; nt < 8; nt++)
#pragma unroll
                for (int e2 = 0; e2 < 4; e2++) {
                    float t = __fmaf_rn(-2.f, acc[mt][nt][e2], bkv[nt][e2 & 1]);
                    int h = e2 >> 1;
                    if (t <= runBest[mt * 2 + h] + MARGIN) {
                        int r = wm * 32 + mt * 16 + g + 8 * h;
                        int k = kbase + nt * 8 + (e2 & 1);
                        int pos = atomicAdd(&sCnt[r], 1);
                        if (pos < 16) sCand[r * 16 + pos] = (unsigned short)k;
                    }
                }
    }
    __syncthreads();
    if (tid < 128) {
        int n = n0 + tid;
        int c = sCnt[tid];
        g_cnt[n] = c;
        int m = (c > 16) ? 16 : c;
        for (int i = 0; i < m; i++) g_cand[n][i] = sCand[tid * 16 + i];
    }
}

// ---------------- exact rescore (R4's bit-exact chain among candidates) ----------------
__global__ __launch_bounds__(128) void k_rescore(const float* __restrict__ x,
                                                 const float* __restrict__ e) {
    int n = blockIdx.x * 128 + threadIdx.x;
    int c = g_cnt[n];
    if (c == 1) { g_idx[n] = g_cand[n][0]; return; }
    int b = n >> 10, hw = n & 1023;
    const float* xp = x + (size_t)b * DIM * HW + hw;
    float an = g_rowsq[n];
    int best = 0;
    float bestS = CUDART_INF_F;
    if (c <= 4 && c >= 1) {
        int kk[4];
        int kA = g_cand[n][0];
#pragma unroll
        for (int i = 0; i < 4; i++) kk[i] = (i < c) ? (int)g_cand[n][i] : kA;
        const float* e0 = e + (size_t)kk[0] * DIM;
        const float* e1 = e + (size_t)kk[1] * DIM;
        const float* e2 = e + (size_t)kk[2] * DIM;
        const float* e3 = e + (size_t)kk[3] * DIM;
        float a0 = 0.f, a1 = 0.f, a2 = 0.f, a3 = 0.f;
#pragma unroll 4
        for (int cc = 0; cc < DIM; cc++) {
            float xv = xp[cc * HW];
            a0 = __fmaf_rn(xv, e0[cc], a0);
            a1 = __fmaf_rn(xv, e1[cc], a1);
            a2 = __fmaf_rn(xv, e2[cc], a2);
            a3 = __fmaf_rn(xv, e3[cc], a3);
        }
        float av[4] = {a0, a1, a2, a3};
#pragma unroll
        for (int i = 0; i < 4; i++) {
            if (i < c) {
                float s = __fsub_rn(__fadd_rn(an, g_embsq[kk[i]]), __fmul_rn(2.0f, av[i]));
                if (s < bestS || (s == bestS && kk[i] < best)) { bestS = s; best = kk[i]; }
            }
        }
    } else {
        int m = (c > 16) ? KCODES : c;
        for (int i = 0; i < m; i++) {
            int k = (c > 16) ? i : (int)g_cand[n][i];
            const float* ep = e + (size_t)k * DIM;
            float acc = 0.f;
#pragma unroll 4
            for (int cc = 0; cc < DIM; cc++)
                acc = __fmaf_rn(xp[cc * HW], ep[cc], acc);
            float s = __fsub_rn(__fadd_rn(an, g_embsq[k]), __fmul_rn(2.0f, acc));
            if (s < bestS || (s == bestS && k < best)) { bestS = s; best = k; }
        }
    }
    g_idx[n] = best;
}

// ---------------- outputs (unchanged from passing R4) ----------------
__global__ __launch_bounds__(128) void k_out(const float* __restrict__ x,
                                             const float* __restrict__ emb,
                                             float* __restrict__ out) {
    int n = blockIdx.x * 128 + threadIdx.x;
    int b = n >> 10, hw = n & 1023;
    const float* xp = x + (size_t)b * DIM * HW + hw;
    float* qp = out + 1 + (size_t)b * DIM * HW + hw;
    int idx = g_idx[n];
    const float* ep = emb + (size_t)idx * DIM;
    double ssum = 0.0;
#pragma unroll 4
    for (int c = 0; c < DIM; c++) {
        float in = xp[c * HW];
        float q  = ep[c];
        float d  = __fsub_rn(q, in);
        float st = __fadd_rn(in, d);
        qp[c * HW] = st;
        float dd = __fmul_rn(d, d);
        ssum += (double)dd;
    }
    out[1 + (size_t)N_TOTAL * DIM + (size_t)n * KCODES + idx] = 1.0f;

    __shared__ double sred[128];
    sred[threadIdx.x] = ssum;
    __syncthreads();
    for (int s = 64; s > 0; s >>= 1) {
        if (threadIdx.x < s) sred[threadIdx.x] += sred[threadIdx.x + s];
        __syncthreads();
    }
    if (threadIdx.x == 0) g_partial[blockIdx.x] = sred[0];
}

__global__ void k_loss(float* __restrict__ out) {
    __shared__ double sred[256];
    sred[threadIdx.x] = g_partial[threadIdx.x];
    __syncthreads();
    for (int s = 128; s > 0; s >>= 1) {
        if (threadIdx.x < s) sred[threadIdx.x] += sred[threadIdx.x + s];
        __syncthreads();
    }
    if (threadIdx.x == 0) {
        double m = sred[0] / (double)((long long)N_TOTAL * DIM);
        out[0] = (float)(m + 0.25 * m);
    }
}

extern "C" void kernel_launch(void* const* d_in, const int* in_sizes, int n_in,
                              void* d_out, int out_size) {
    const float* x = (const float*)d_in[0];
    const float* e = (const float*)d_in[1];
    if (n_in >= 2 && in_sizes[0] == KCODES * DIM && in_sizes[1] == N_TOTAL * DIM) {
        x = (const float*)d_in[1];
        e = (const float*)d_in[0];
    }
    float* out = (float*)d_out;

    cudaFuncSetAttribute(k_gemm, cudaFuncAttributeMaxDynamicSharedMemorySize, SMEM_BYTES);

    k_pack_x<<<N_TOTAL / 128, 256>>>(x);
    k_pack_e<<<(KCODES * 128 + 255) / 256, 256>>>(e);
    k_rowsq<<<N_TOTAL / 256, 256>>>(x);
    k_embsq<<<KCODES / 256, 256>>>(e);

    long long encN = (long long)N_TOTAL * KCODES;
    k_zero<<<(unsigned)((encN + 255) / 256), 256>>>(
        out + 1 + (size_t)N_TOTAL * DIM, encN);

    k_gemm<<<N_TOTAL / 128, 256, SMEM_BYTES>>>();
    k_rescore<<<N_TOTAL / 128, 128>>>(x, e);
    k_out<<<N_TOTAL / 128, 128>>>(x, e, out);
    k_loss<<<1, 256>>>(out);
}

// round 9
// speedup vs baseline: 1.4919x; 1.4919x over previous
#include <cuda_runtime.h>
#include <cuda_bf16.h>
#include <math_constants.h>
#include <cstdint>

#define N_TOTAL 32768
#define DIM     256
#define KCODES  1024
#define HW      1024
#define MARGIN  2.5e-3f

// ---------------- scratch ----------------
__device__ __align__(16) uint32_t g_epack[(size_t)KCODES * 128];  // bf16x2 codes, K-major
__device__ float    g_rowsq[N_TOTAL];
__device__ float    g_embsq[KCODES];
__device__ int      g_idx[N_TOTAL];
__device__ unsigned short g_cand[N_TOTAL][16];
__device__ int      g_cnt[N_TOTAL];
__device__ double   g_partial[256];

// ---------------- cp.async helpers (sm_80+, legal on plain sm_103 target) ----
__device__ __forceinline__ void cp16(uint32_t saddr, const void* gaddr) {
    asm volatile("cp.async.cg.shared.global [%0], [%1], 16;" :: "r"(saddr), "l"(gaddr));
}
#define CP_COMMIT() asm volatile("cp.async.commit_group;" ::: "memory")
#define CP_WAIT(n)  asm volatile("cp.async.wait_group %0;" :: "n"(n) : "memory")

// ---------------- prepack embedding to bf16 (single term) ----------------
__global__ void k_pack_e(const float* __restrict__ e) {
    int id = blockIdx.x * blockDim.x + threadIdx.x;
    if (id >= KCODES * 128) return;
    int k = id >> 7, cp = id & 127;
    float f0 = e[(size_t)k * DIM + 2 * cp];
    float f1 = e[(size_t)k * DIM + 2 * cp + 1];
    __nv_bfloat16 h0 = __float2bfloat16_rn(f0);
    __nv_bfloat16 h1 = __float2bfloat16_rn(f1);
    g_epack[(size_t)k * 128 + cp] =
        ((uint32_t)__bfloat16_as_ushort(h1) << 16) | __bfloat16_as_ushort(h0);
}

// ---------------- embsq (exact sequential order; latency-spread grid) -------
__global__ void k_embsq(const float* __restrict__ e) {
    int k = blockIdx.x * blockDim.x + threadIdx.x;
    if (k >= KCODES) return;
    const float* p = e + (size_t)k * DIM;
    float acc = 0.f;
#pragma unroll 8
    for (int c = 0; c < DIM; c++) {
        float v = p[c];
        acc = __fadd_rn(acc, __fmul_rn(v, v));
    }
    g_embsq[k] = acc;
}

// scalar zero: encodings base is only 4B-aligned (out + 1 + 8388608)
__global__ void k_zero(float* __restrict__ p, long long count) {
    long long i = (long long)blockIdx.x * blockDim.x + threadIdx.x;
    if (i < count) p[i] = 0.0f;
}

// ---------------- fused: x->bf16 staging + rowsq + HMMA GEMM + argmin -------
// 256 blocks x 512 threads. Warp (wm,wn): rows [wm*32,+32), codes [wn*32,+32)
// per 128-code panel. A resident in SMEM; B whole-panel cp.async double-buffer.
#define SA_ST     132
#define SB_OFF    (128 * SA_ST)            // 16896
#define SB_BUF    (128 * SA_ST)            // 16896 u32 per buffer
#define SBK_OFF   (SB_OFF + 2 * SB_BUF)    // 50688
#define SMINW_OFF (SBK_OFF + 1024)         // 51712 : float [128][4]
#define SBEST_OFF (SMINW_OFF + 512)        // 52224 : float [128]
#define SCNT_OFF  (SBEST_OFF + 128)        // 52352
#define SCAND_OFF (SCNT_OFF + 128)         // 52480 : u16 [128][16]
#define SMEM_U32  (SCAND_OFF + 1024)       // 53504
#define SMEM_BYTES (SMEM_U32 * 4)          // 214016 B

__global__ __launch_bounds__(512, 1) void k_gemm(const float* __restrict__ x) {
    extern __shared__ __align__(16) uint32_t sm[];
    uint32_t* sA   = sm;
    float*    sBk  = (float*)(sm + SBK_OFF);
    float*    sMnW = (float*)(sm + SMINW_OFF);
    float*    sBest= (float*)(sm + SBEST_OFF);
    int*      sCnt = (int*)(sm + SCNT_OFF);
    unsigned short* sCand = (unsigned short*)(sm + SCAND_OFF);

    int tid = threadIdx.x;
    int lane = tid & 31, w = tid >> 5;
    int g = lane >> 2, tg = lane & 3;
    int wm = w & 3, wn = w >> 2;
    int n0 = blockIdx.x * 128;

    uint32_t smu;
    asm("{ .reg .u64 t; cvta.to.shared.u64 t, %1; cvt.u32.u64 %0, t; }"
        : "=r"(smu) : "l"(sm));

    // kick off panel 0 -> buf0 immediately
    {
        const uint32_t* gsrc = g_epack;
#pragma unroll
        for (int i = 0; i < 8; i++) {
            int seg = tid + i * 512, code = seg >> 5, j = seg & 31;
            cp16(smu + (uint32_t)(SB_OFF + code * SA_ST + j * 4) * 4,
                 gsrc + code * 128 + j * 4);
        }
        CP_COMMIT();
    }

    for (int i = tid; i < KCODES; i += 512) sBk[i] = g_embsq[i];
    if (tid < 128) { sCnt[tid] = 0; sBest[tid] = CUDART_INF_F; }

    // ---- A staging + rowsq; sT aliased into B buffer 1 (free until panel 1) --
    float* sT = (float*)(sm + SB_OFF + SB_BUF);   // 32 x 129 f32 = 16512 B
    int b = n0 >> 10, hw0 = n0 & 1023;
    const float* xb = x + (size_t)b * DIM * HW + hw0;
    float rs = 0.f;
    for (int cc0 = 0; cc0 < 8; cc0++) {
        __syncthreads();
#pragma unroll
        for (int i = 0; i < 8; i++) {
            int idx = tid + i * 512, ci = idx >> 7, nn = idx & 127;
            sT[ci * 129 + nn] = xb[(cc0 * 32 + ci) * HW + nn];
        }
        __syncthreads();
#pragma unroll
        for (int i = 0; i < 4; i++) {
            int idx = tid + i * 512, nn = idx >> 4, cp = idx & 15;
            float f0 = sT[(2 * cp) * 129 + nn];
            float f1 = sT[(2 * cp + 1) * 129 + nn];
            __nv_bfloat16 h0 = __float2bfloat16_rn(f0);
            __nv_bfloat16 h1 = __float2bfloat16_rn(f1);
            sA[nn * SA_ST + cc0 * 16 + cp] =
                ((uint32_t)__bfloat16_as_ushort(h1) << 16) | __bfloat16_as_ushort(h0);
        }
        if (tid < 128) {   // exact sequential rowsq, c ascending
#pragma unroll
            for (int c = 0; c < 32; c++) {
                float v = sT[c * 129 + tid];
                rs = __fadd_rn(rs, __fmul_rn(v, v));
            }
        }
    }
    __syncthreads();
    if (tid < 128) g_rowsq[n0 + tid] = rs;

    // panel 1 -> buf1 (sT region now dead)
    {
        const uint32_t* gsrc = g_epack + (size_t)128 * 128;
#pragma unroll
        for (int i = 0; i < 8; i++) {
            int seg = tid + i * 512, code = seg >> 5, j = seg & 31;
            cp16(smu + (uint32_t)(SB_OFF + SB_BUF + code * SA_ST + j * 4) * 4,
                 gsrc + code * 128 + j * 4);
        }
        CP_COMMIT();
    }

    for (int p = 0; p < 8; p++) {
        if (p < 7) CP_WAIT(1); else CP_WAIT(0);
        __syncthreads();
        const uint32_t* Bbuf = sm + SB_OFF + (p & 1) * SB_BUF;

        float acc[2][4][4];
#pragma unroll
        for (int mt = 0; mt < 2; mt++)
#pragma unroll
            for (int nt = 0; nt < 4; nt++)
#pragma unroll
                for (int e2 = 0; e2 < 4; e2++) acc[mt][nt][e2] = 0.f;

        const uint32_t* Ab = sA + (wm * 32 + g) * SA_ST;
        const uint32_t* Bb = Bbuf + (wn * 32 + g) * SA_ST;
#pragma unroll
        for (int ks = 0; ks < 16; ks++) {
            uint32_t a[2][4];
#pragma unroll
            for (int mt = 0; mt < 2; mt++) {
                const uint32_t* ap = Ab + mt * 16 * SA_ST + ks * 8 + tg;
                a[mt][0] = ap[0];
                a[mt][1] = ap[8 * SA_ST];
                a[mt][2] = ap[4];
                a[mt][3] = ap[8 * SA_ST + 4];
            }
#pragma unroll
            for (int nt = 0; nt < 4; nt++) {
                uint32_t b0 = Bb[nt * 8 * SA_ST + ks * 8 + tg];
                uint32_t b1 = Bb[nt * 8 * SA_ST + ks * 8 + tg + 4];
#pragma unroll
                for (int mt = 0; mt < 2; mt++) {
                    asm volatile(
                        "mma.sync.aligned.m16n8k16.row.col.f32.bf16.bf16.f32 "
                        "{%0,%1,%2,%3}, {%4,%5,%6,%7}, {%8,%9}, {%0,%1,%2,%3};"
                        : "+f"(acc[mt][nt][0]), "+f"(acc[mt][nt][1]),
                          "+f"(acc[mt][nt][2]), "+f"(acc[mt][nt][3])
                        : "r"(a[mt][0]), "r"(a[mt][1]), "r"(a[mt][2]), "r"(a[mt][3]),
                          "r"(b0), "r"(b1));
                }
            }
        }

        // ---- phase 1: per-(row,warp) min -> sMnW ----
        int kb = p * 128 + wn * 32 + 2 * tg;
        float bkv[4][2];
#pragma unroll
        for (int nt = 0; nt < 4; nt++) {
            bkv[nt][0] = sBk[kb + nt * 8];
            bkv[nt][1] = sBk[kb + nt * 8 + 1];
        }
        float mn[4] = {CUDART_INF_F, CUDART_INF_F, CUDART_INF_F, CUDART_INF_F};
#pragma unroll
        for (int mt = 0; mt < 2; mt++)
#pragma unroll
            for (int nt = 0; nt < 4; nt++) {
                float t0 = __fmaf_rn(-2.f, acc[mt][nt][0], bkv[nt][0]);
                float t1 = __fmaf_rn(-2.f, acc[mt][nt][1], bkv[nt][1]);
                float t2 = __fmaf_rn(-2.f, acc[mt][nt][2], bkv[nt][0]);
                float t3 = __fmaf_rn(-2.f, acc[mt][nt][3], bkv[nt][1]);
                mn[mt * 2]     = fminf(mn[mt * 2], fminf(t0, t1));
                mn[mt * 2 + 1] = fminf(mn[mt * 2 + 1], fminf(t2, t3));
            }
#pragma unroll
        for (int i = 0; i < 4; i++) {
            mn[i] = fminf(mn[i], __shfl_xor_sync(0xffffffffu, mn[i], 1));
            mn[i] = fminf(mn[i], __shfl_xor_sync(0xffffffffu, mn[i], 2));
        }
        if (tg == 0) {
#pragma unroll
            for (int mt = 0; mt < 2; mt++)
#pragma unroll
                for (int h = 0; h < 2; h++) {
                    int r = wm * 32 + mt * 16 + g + 8 * h;
                    sMnW[r * 4 + wn] = mn[mt * 2 + h];
                }
        }
        __syncthreads();

        // prefetch panel p+2 into the buffer just consumed (B reads all done)
        if (p + 2 < 8) {
            const uint32_t* gsrc = g_epack + (size_t)(p + 2) * 128 * 128;
            uint32_t dst = smu + (uint32_t)(SB_OFF + (p & 1) * SB_BUF) * 4;
#pragma unroll
            for (int i = 0; i < 8; i++) {
                int seg = tid + i * 512, code = seg >> 5, j = seg & 31;
                cp16(dst + (uint32_t)(code * SA_ST + j * 4) * 4,
                     gsrc + code * 128 + j * 4);
            }
            CP_COMMIT();
        }

        // ---- phase 2: capture candidates vs global running best ----
        float thr[4];
#pragma unroll
        for (int mt = 0; mt < 2; mt++)
#pragma unroll
            for (int h = 0; h < 2; h++) {
                int r = wm * 32 + mt * 16 + g + 8 * h;
                float t4 = fminf(fminf(sMnW[r * 4 + 0], sMnW[r * 4 + 1]),
                                 fminf(sMnW[r * 4 + 2], sMnW[r * 4 + 3]));
                thr[mt * 2 + h] = fminf(sBest[r], t4);
            }
#pragma unroll
        for (int mt = 0; mt < 2; mt++)
#pragma unroll
            for (int nt = 0; nt < 4; nt++)
#pragma unroll
                for (int e2 = 0; e2 < 4; e2++) {
                    float t = __fmaf_rn(-2.f, acc[mt][nt][e2], bkv[nt][e2 & 1]);
                    int h = e2 >> 1;
                    if (t <= thr[mt * 2 + h] + MARGIN) {
                        int r = wm * 32 + mt * 16 + g + 8 * h;
                        int k = kb + nt * 8 + (e2 & 1);
                        int pos = atomicAdd(&sCnt[r], 1);
                        if (pos < 16) sCand[r * 16 + pos] = (unsigned short)k;
                    }
                }
        __syncthreads();
        if (wn == 0 && tg == 0) {
#pragma unroll
            for (int mt = 0; mt < 2; mt++)
#pragma unroll
                for (int h = 0; h < 2; h++) {
                    int r = wm * 32 + mt * 16 + g + 8 * h;
                    sBest[r] = thr[mt * 2 + h];
                }
        }
        // next loop-top __syncthreads orders sBest/sMnW for the next panel
    }
    __syncthreads();
    if (tid < 128) {
        int n = n0 + tid;
        int c = sCnt[tid];
        g_cnt[n] = c;
        int m = (c > 16) ? 16 : c;
        for (int i = 0; i < m; i++) g_cand[n][i] = sCand[tid * 16 + i];
    }
}

// ---------------- exact rescore (R4's bit-exact chain among candidates) -----
__global__ __launch_bounds__(128) void k_rescore(const float* __restrict__ x,
                                                 const float* __restrict__ e) {
    int n = blockIdx.x * 128 + threadIdx.x;
    int c = g_cnt[n];
    if (c == 1) { g_idx[n] = g_cand[n][0]; return; }
    int b = n >> 10, hw = n & 1023;
    const float* xp = x + (size_t)b * DIM * HW + hw;
    float an = g_rowsq[n];
    int best = 0;
    float bestS = CUDART_INF_F;
    if (c <= 4 && c >= 1) {
        int kk[4];
        int kA = g_cand[n][0];
#pragma unroll
        for (int i = 0; i < 4; i++) kk[i] = (i < c) ? (int)g_cand[n][i] : kA;
        const float* e0 = e + (size_t)kk[0] * DIM;
        const float* e1 = e + (size_t)kk[1] * DIM;
        const float* e2 = e + (size_t)kk[2] * DIM;
        const float* e3 = e + (size_t)kk[3] * DIM;
        float a0 = 0.f, a1 = 0.f, a2 = 0.f, a3 = 0.f;
#pragma unroll 4
        for (int cc = 0; cc < DIM; cc++) {
            float xv = xp[cc * HW];
            a0 = __fmaf_rn(xv, e0[cc], a0);
            a1 = __fmaf_rn(xv, e1[cc], a1);
            a2 = __fmaf_rn(xv, e2[cc], a2);
            a3 = __fmaf_rn(xv, e3[cc], a3);
        }
        float av[4] = {a0, a1, a2, a3};
#pragma unroll
        for (int i = 0; i < 4; i++) {
            if (i < c) {
                float s = __fsub_rn(__fadd_rn(an, g_embsq[kk[i]]), __fmul_rn(2.0f, av[i]));
                if (s < bestS || (s == bestS && kk[i] < best)) { bestS = s; best = kk[i]; }
            }
        }
    } else {
        int m = (c > 16) ? KCODES : c;
        for (int i = 0; i < m; i++) {
            int k = (c > 16) ? i : (int)g_cand[n][i];
            const float* ep = e + (size_t)k * DIM;
            float acc = 0.f;
#pragma unroll 4
            for (int cc = 0; cc < DIM; cc++)
                acc = __fmaf_rn(xp[cc * HW], ep[cc], acc);
            float s = __fsub_rn(__fadd_rn(an, g_embsq[k]), __fmul_rn(2.0f, acc));
            if (s < bestS || (s == bestS && k < best)) { bestS = s; best = k; }
        }
    }
    g_idx[n] = best;
}

// ---------------- outputs (unchanged from passing R4/R8) --------------------
__global__ __launch_bounds__(128) void k_out(const float* __restrict__ x,
                                             const float* __restrict__ emb,
                                             float* __restrict__ out) {
    int n = blockIdx.x * 128 + threadIdx.x;
    int b = n >> 10, hw = n & 1023;
    const float* xp = x + (size_t)b * DIM * HW + hw;
    float* qp = out + 1 + (size_t)b * DIM * HW + hw;
    int idx = g_idx[n];
    const float* ep = emb + (size_t)idx * DIM;
    double ssum = 0.0;
#pragma unroll 4
    for (int c = 0; c < DIM; c++) {
        float in = xp[c * HW];
        float q  = ep[c];
        float d  = __fsub_rn(q, in);
        float st = __fadd_rn(in, d);
        qp[c * HW] = st;
        float dd = __fmul_rn(d, d);
        ssum += (double)dd;
    }
    out[1 + (size_t)N_TOTAL * DIM + (size_t)n * KCODES + idx] = 1.0f;

    __shared__ double sred[128];
    sred[threadIdx.x] = ssum;
    __syncthreads();
    for (int s = 64; s > 0; s >>= 1) {
        if (threadIdx.x < s) sred[threadIdx.x] += sred[threadIdx.x + s];
        __syncthreads();
    }
    if (threadIdx.x == 0) g_partial[blockIdx.x] = sred[0];
}

__global__ void k_loss(float* __restrict__ out) {
    __shared__ double sred[256];
    sred[threadIdx.x] = g_partial[threadIdx.x];
    __syncthreads();
    for (int s = 128; s > 0; s >>= 1) {
        if (threadIdx.x < s) sred[threadIdx.x] += sred[threadIdx.x + s];
        __syncthreads();
    }
    if (threadIdx.x == 0) {
        double m = sred[0] / (double)((long long)N_TOTAL * DIM);
        out[0] = (float)(m + 0.25 * m);
    }
}

extern "C" void kernel_launch(void* const* d_in, const int* in_sizes, int n_in,
                              void* d_out, int out_size) {
    const float* x = (const float*)d_in[0];
    const float* e = (const float*)d_in[1];
    if (n_in >= 2 && in_sizes[0] == KCODES * DIM && in_sizes[1] == N_TOTAL * DIM) {
        x = (const float*)d_in[1];
        e = (const float*)d_in[0];
    }
    float* out = (float*)d_out;

    cudaFuncSetAttribute(k_gemm, cudaFuncAttributeMaxDynamicSharedMemorySize, SMEM_BYTES);

    k_pack_e<<<(KCODES * 128 + 255) / 256, 256>>>(e);
    k_embsq<<<32, 32>>>(e);

    long long encN = (long long)N_TOTAL * KCODES;
    k_zero<<<(unsigned)((encN + 255) / 256), 256>>>(
        out + 1 + (size_t)N_TOTAL * DIM, encN);

    k_gemm<<<N_TOTAL / 128, 512, SMEM_BYTES>>>(x);
    k_rescore<<<N_TOTAL / 128, 128>>>(x, e);
    k_out<<<N_TOTAL / 128, 128>>>(x, e, out);
    k_loss<<<1, 256>>>(out);
}

// round 10
// speedup vs baseline: 2.0364x; 1.3650x over previous
#include <cuda_runtime.h>
#include <cuda_bf16.h>
#include <math_constants.h>
#include <cstdint>

#define N_TOTAL 32768
#define DIM     256
#define KCODES  1024
#define HW      1024
#define MARGIN  2.5e-3f

// ---------------- scratch ----------------
__device__ __align__(16) uint32_t g_epack[(size_t)KCODES * 128];  // bf16x2 codes, K-major
__device__ float    g_embsq[KCODES];
__device__ int      g_idx[N_TOTAL];
__device__ double   g_partial[256];

// ---------------- cp.async helpers ----------------
__device__ __forceinline__ void cp16(uint32_t saddr, const void* gaddr) {
    asm volatile("cp.async.cg.shared.global [%0], [%1], 16;" :: "r"(saddr), "l"(gaddr));
}
#define CP_COMMIT() asm volatile("cp.async.commit_group;" ::: "memory")
#define CP_WAIT(n)  asm volatile("cp.async.wait_group %0;" :: "n"(n) : "memory")

// order-preserving float -> u32; key = (ord(score) << 32) | idx  (min = best, ties -> min idx)
__device__ __forceinline__ unsigned long long mkkey(float s, int k) {
    unsigned u = __float_as_uint(s);
    u = (u & 0x80000000u) ? ~u : (u | 0x80000000u);
    return ((unsigned long long)u << 32) | (unsigned)k;
}

// ---------------- fused pack(e->bf16) + embsq (exact sequential order) ------
__global__ void k_prep(const float* __restrict__ e) {
    int k = blockIdx.x * blockDim.x + threadIdx.x;
    if (k >= KCODES) return;
    const float* p = e + (size_t)k * DIM;
    uint32_t* row = g_epack + (size_t)k * 128;
    float acc = 0.f;
#pragma unroll 8
    for (int cp = 0; cp < 128; cp++) {
        float f0 = p[2 * cp], f1 = p[2 * cp + 1];
        acc = __fadd_rn(acc, __fmul_rn(f0, f0));
        acc = __fadd_rn(acc, __fmul_rn(f1, f1));
        __nv_bfloat16 h0 = __float2bfloat16_rn(f0);
        __nv_bfloat16 h1 = __float2bfloat16_rn(f1);
        row[cp] = ((uint32_t)__bfloat16_as_ushort(h1) << 16) | __bfloat16_as_ushort(h0);
    }
    g_embsq[k] = acc;
}

// ---------------- encodings zero: vectorized around 4B-misaligned base ------
__global__ void k_zero_enc(float* __restrict__ enc, long long n) {
    uintptr_t a = (uintptr_t)enc;
    int head = (int)(((16 - (a & 15)) & 15) >> 2);
    if (head > n) head = (int)n;
    long long nb = (n - head) >> 2;
    uint4* b4 = (uint4*)(enc + head);
    long long T = (long long)gridDim.x * blockDim.x;
    long long t = (long long)blockIdx.x * blockDim.x + threadIdx.x;
    for (long long i = t; i < nb; i += T) b4[i] = make_uint4(0, 0, 0, 0);
    long long ts = head + nb * 4;
    if (t < head) enc[t] = 0.0f;
    long long rem = n - ts;
    if (t >= head && t < head + rem) enc[ts + (t - head)] = 0.0f;
}

// ---------------- fused: staging + rowsq + HMMA + argmin + exact rescore ----
#define SA_ST     132
#define SB_OFF    (128 * SA_ST)            // 16896
#define SB_BUF    (128 * SA_ST)
#define SBK_OFF   (SB_OFF + 2 * SB_BUF)    // 50688
#define SMINW_OFF (SBK_OFF + 1024)         // 51712
#define SBEST_OFF (SMINW_OFF + 512)        // 52224
#define SCNT_OFF  (SBEST_OFF + 128)        // 52352
#define SCAND_OFF (SCNT_OFF + 128)         // 52480
#define SAN_OFF   (SCAND_OFF + 1024)       // 53504
#define SKEY_OFF  (SAN_OFF + 128)          // 53632 (x4 = 214528 B, 8B-aligned)
#define SOVF_OFF  (SKEY_OFF + 256)         // 53888 : [0]=count, [1..128]=rows
#define SMEM_U32  (SOVF_OFF + 132)         // 54020
#define SMEM_BYTES (SMEM_U32 * 4)          // 216080 B

__global__ __launch_bounds__(512, 1) void k_gemm(const float* __restrict__ x,
                                                 const float* __restrict__ e) {
    extern __shared__ __align__(16) uint32_t sm[];
    uint32_t* sA   = sm;
    float*    sBk  = (float*)(sm + SBK_OFF);
    float*    sMnW = (float*)(sm + SMINW_OFF);
    float*    sBest= (float*)(sm + SBEST_OFF);
    int*      sCnt = (int*)(sm + SCNT_OFF);
    unsigned short* sCand = (unsigned short*)(sm + SCAND_OFF);
    float*    sAn  = (float*)(sm + SAN_OFF);
    unsigned long long* sKey = (unsigned long long*)(sm + SKEY_OFF);
    int*      sOvf = (int*)(sm + SOVF_OFF);

    int tid = threadIdx.x;
    int lane = tid & 31, w = tid >> 5;
    int g = lane >> 2, tg = lane & 3;
    int wm = w & 3, wn = w >> 2;
    int n0 = blockIdx.x * 128;

    uint32_t smu;
    asm("{ .reg .u64 t; cvta.to.shared.u64 t, %1; cvt.u32.u64 %0, t; }"
        : "=r"(smu) : "l"(sm));

    // kick off panel 0 -> buf0
    {
        const uint32_t* gsrc = g_epack;
#pragma unroll
        for (int i = 0; i < 8; i++) {
            int seg = tid + i * 512, code = seg >> 5, j = seg & 31;
            cp16(smu + (uint32_t)(SB_OFF + code * SA_ST + j * 4) * 4,
                 gsrc + code * 128 + j * 4);
        }
        CP_COMMIT();
    }

    for (int i = tid; i < KCODES; i += 512) sBk[i] = g_embsq[i];
    if (tid < 128) { sCnt[tid] = 0; sBest[tid] = CUDART_INF_F; }
    if (tid == 0) sOvf[0] = 0;

    // ---- A staging + rowsq; sT aliased into B buffer 1 ----
    float* sT = (float*)(sm + SB_OFF + SB_BUF);
    int b = n0 >> 10, hw0 = n0 & 1023;
    const float* xb = x + (size_t)b * DIM * HW + hw0;
    float rs = 0.f;
    for (int cc0 = 0; cc0 < 8; cc0++) {
        __syncthreads();
#pragma unroll
        for (int i = 0; i < 8; i++) {
            int idx = tid + i * 512, ci = idx >> 7, nn = idx & 127;
            sT[ci * 129 + nn] = xb[(cc0 * 32 + ci) * HW + nn];
        }
        __syncthreads();
#pragma unroll
        for (int i = 0; i < 4; i++) {
            int idx = tid + i * 512, nn = idx >> 4, cp = idx & 15;
            float f0 = sT[(2 * cp) * 129 + nn];
            float f1 = sT[(2 * cp + 1) * 129 + nn];
            __nv_bfloat16 h0 = __float2bfloat16_rn(f0);
            __nv_bfloat16 h1 = __float2bfloat16_rn(f1);
            sA[nn * SA_ST + cc0 * 16 + cp] =
                ((uint32_t)__bfloat16_as_ushort(h1) << 16) | __bfloat16_as_ushort(h0);
        }
        if (tid < 128) {   // exact sequential rowsq
#pragma unroll
            for (int c = 0; c < 32; c++) {
                float v = sT[c * 129 + tid];
                rs = __fadd_rn(rs, __fmul_rn(v, v));
            }
        }
    }
    __syncthreads();
    if (tid < 128) sAn[tid] = rs;

    // panel 1 -> buf1
    {
        const uint32_t* gsrc = g_epack + (size_t)128 * 128;
#pragma unroll
        for (int i = 0; i < 8; i++) {
            int seg = tid + i * 512, code = seg >> 5, j = seg & 31;
            cp16(smu + (uint32_t)(SB_OFF + SB_BUF + code * SA_ST + j * 4) * 4,
                 gsrc + code * 128 + j * 4);
        }
        CP_COMMIT();
    }

    for (int p = 0; p < 8; p++) {
        if (p < 7) CP_WAIT(1); else CP_WAIT(0);
        __syncthreads();
        const uint32_t* Bbuf = sm + SB_OFF + (p & 1) * SB_BUF;

        float acc[2][4][4];
#pragma unroll
        for (int mt = 0; mt < 2; mt++)
#pragma unroll
            for (int nt = 0; nt < 4; nt++)
#pragma unroll
                for (int e2 = 0; e2 < 4; e2++) acc[mt][nt][e2] = 0.f;

        const uint32_t* Ab = sA + (wm * 32 + g) * SA_ST;
        const uint32_t* Bb = Bbuf + (wn * 32 + g) * SA_ST;
#pragma unroll
        for (int ks = 0; ks < 16; ks++) {
            uint32_t a[2][4];
#pragma unroll
            for (int mt = 0; mt < 2; mt++) {
                const uint32_t* ap = Ab + mt * 16 * SA_ST + ks * 8 + tg;
                a[mt][0] = ap[0];
                a[mt][1] = ap[8 * SA_ST];
                a[mt][2] = ap[4];
                a[mt][3] = ap[8 * SA_ST + 4];
            }
#pragma unroll
            for (int nt = 0; nt < 4; nt++) {
                uint32_t b0 = Bb[nt * 8 * SA_ST + ks * 8 + tg];
                uint32_t b1 = Bb[nt * 8 * SA_ST + ks * 8 + tg + 4];
#pragma unroll
                for (int mt = 0; mt < 2; mt++) {
                    asm volatile(
                        "mma.sync.aligned.m16n8k16.row.col.f32.bf16.bf16.f32 "
                        "{%0,%1,%2,%3}, {%4,%5,%6,%7}, {%8,%9}, {%0,%1,%2,%3};"
                        : "+f"(acc[mt][nt][0]), "+f"(acc[mt][nt][1]),
                          "+f"(acc[mt][nt][2]), "+f"(acc[mt][nt][3])
                        : "r"(a[mt][0]), "r"(a[mt][1]), "r"(a[mt][2]), "r"(a[mt][3]),
                          "r"(b0), "r"(b1));
                }
            }
        }

        // ---- phase 1: per-(row,warp) min ----
        int kb = p * 128 + wn * 32 + 2 * tg;
        float bkv[4][2];
#pragma unroll
        for (int nt = 0; nt < 4; nt++) {
            bkv[nt][0] = sBk[kb + nt * 8];
            bkv[nt][1] = sBk[kb + nt * 8 + 1];
        }
        float mn[4] = {CUDART_INF_F, CUDART_INF_F, CUDART_INF_F, CUDART_INF_F};
#pragma unroll
        for (int mt = 0; mt < 2; mt++)
#pragma unroll
            for (int nt = 0; nt < 4; nt++) {
                float t0 = __fmaf_rn(-2.f, acc[mt][nt][0], bkv[nt][0]);
                float t1 = __fmaf_rn(-2.f, acc[mt][nt][1], bkv[nt][1]);
                float t2 = __fmaf_rn(-2.f, acc[mt][nt][2], bkv[nt][0]);
                float t3 = __fmaf_rn(-2.f, acc[mt][nt][3], bkv[nt][1]);
                mn[mt * 2]     = fminf(mn[mt * 2], fminf(t0, t1));
                mn[mt * 2 + 1] = fminf(mn[mt * 2 + 1], fminf(t2, t3));
            }
#pragma unroll
        for (int i = 0; i < 4; i++) {
            mn[i] = fminf(mn[i], __shfl_xor_sync(0xffffffffu, mn[i], 1));
            mn[i] = fminf(mn[i], __shfl_xor_sync(0xffffffffu, mn[i], 2));
        }
        if (tg == 0) {
#pragma unroll
            for (int mt = 0; mt < 2; mt++)
#pragma unroll
                for (int h = 0; h < 2; h++) {
                    int r = wm * 32 + mt * 16 + g + 8 * h;
                    sMnW[r * 4 + wn] = mn[mt * 2 + h];
                }
        }
        __syncthreads();

        // prefetch panel p+2
        if (p + 2 < 8) {
            const uint32_t* gsrc = g_epack + (size_t)(p + 2) * 128 * 128;
            uint32_t dst = smu + (uint32_t)(SB_OFF + (p & 1) * SB_BUF) * 4;
#pragma unroll
            for (int i = 0; i < 8; i++) {
                int seg = tid + i * 512, code = seg >> 5, j = seg & 31;
                cp16(dst + (uint32_t)(code * SA_ST + j * 4) * 4,
                     gsrc + code * 128 + j * 4);
            }
            CP_COMMIT();
        }

        // ---- phase 2: capture candidates vs global running best ----
        float thr[4];
#pragma unroll
        for (int mt = 0; mt < 2; mt++)
#pragma unroll
            for (int h = 0; h < 2; h++) {
                int r = wm * 32 + mt * 16 + g + 8 * h;
                float t4 = fminf(fminf(sMnW[r * 4 + 0], sMnW[r * 4 + 1]),
                                 fminf(sMnW[r * 4 + 2], sMnW[r * 4 + 3]));
                thr[mt * 2 + h] = fminf(sBest[r], t4);
            }
#pragma unroll
        for (int mt = 0; mt < 2; mt++)
#pragma unroll
            for (int nt = 0; nt < 4; nt++)
#pragma unroll
                for (int e2 = 0; e2 < 4; e2++) {
                    float t = __fmaf_rn(-2.f, acc[mt][nt][e2], bkv[nt][e2 & 1]);
                    int h = e2 >> 1;
                    if (t <= thr[mt * 2 + h] + MARGIN) {
                        int r = wm * 32 + mt * 16 + g + 8 * h;
                        int k = kb + nt * 8 + (e2 & 1);
                        int pos = atomicAdd(&sCnt[r], 1);
                        if (pos < 16) sCand[r * 16 + pos] = (unsigned short)k;
                    }
                }
        __syncthreads();
        if (wn == 0 && tg == 0) {
#pragma unroll
            for (int mt = 0; mt < 2; mt++)
#pragma unroll
                for (int h = 0; h < 2; h++) {
                    int r = wm * 32 + mt * 16 + g + 8 * h;
                    sBest[r] = thr[mt * 2 + h];
                }
        }
    }
    __syncthreads();

    // ---- in-block exact rescore (R4's bit-exact chain) ----
    if (tid < 128) sKey[tid] = 0xFFFFFFFFFFFFFFFFull;
    __syncthreads();

    int rr = tid & 127, slot = tid >> 7;   // 4 slots per row
    int cnt = sCnt[rr];
    const float* xpr = x + (size_t)b * DIM * HW + hw0 + rr;
    if (cnt <= 16) {
        float an = sAn[rr];
        for (int s = slot; s < cnt; s += 4) {
            int k = sCand[rr * 16 + s];
            const float* ep = e + (size_t)k * DIM;
            float a = 0.f;
#pragma unroll 4
            for (int d = 0; d < DIM; d++)
                a = __fmaf_rn(xpr[d * HW], ep[d], a);
            float sc = __fsub_rn(__fadd_rn(an, sBk[k]), __fmul_rn(2.0f, a));
            atomicMin(&sKey[rr], mkkey(sc, k));
        }
    } else if (slot == 0) {
        int pidx = atomicAdd(&sOvf[0], 1);
        sOvf[1 + pidx] = rr;
    }
    __syncthreads();

    // overflow rows: one warp per row, full 1024-code exact scan
    int novf = sOvf[0];
    for (int li = w; li < novf; li += 16) {
        int r2 = sOvf[1 + li];
        const float* xp2 = x + (size_t)b * DIM * HW + hw0 + r2;
        float an2 = sAn[r2];
        unsigned long long bk = 0xFFFFFFFFFFFFFFFFull;
        for (int k = lane; k < KCODES; k += 32) {
            const float* ep = e + (size_t)k * DIM;
            float a = 0.f;
#pragma unroll 4
            for (int d = 0; d < DIM; d++)
                a = __fmaf_rn(xp2[d * HW], ep[d], a);
            float sc = __fsub_rn(__fadd_rn(an2, sBk[k]), __fmul_rn(2.0f, a));
            unsigned long long kk = mkkey(sc, k);
            if (kk < bk) bk = kk;
        }
#pragma unroll
        for (int m = 16; m > 0; m >>= 1) {
            unsigned long long o = __shfl_xor_sync(0xffffffffu, bk, m);
            if (o < bk) bk = o;
        }
        if (lane == 0) sKey[r2] = bk;
    }
    __syncthreads();
    if (tid < 128) g_idx[n0 + tid] = (int)(sKey[tid] & 0xFFFFFFFFu);
}

// ---------------- outputs (unchanged from passing R4/R9) --------------------
__global__ __launch_bounds__(128) void k_out(const float* __restrict__ x,
                                             const float* __restrict__ emb,
                                             float* __restrict__ out) {
    int n = blockIdx.x * 128 + threadIdx.x;
    int b = n >> 10, hw = n & 1023;
    const float* xp = x + (size_t)b * DIM * HW + hw;
    float* qp = out + 1 + (size_t)b * DIM * HW + hw;
    int idx = g_idx[n];
    const float* ep = emb + (size_t)idx * DIM;
    double ssum = 0.0;
#pragma unroll 4
    for (int c = 0; c < DIM; c++) {
        float in = xp[c * HW];
        float q  = ep[c];
        float d  = __fsub_rn(q, in);
        float st = __fadd_rn(in, d);
        qp[c * HW] = st;
        float dd = __fmul_rn(d, d);
        ssum += (double)dd;
    }
    out[1 + (size_t)N_TOTAL * DIM + (size_t)n * KCODES + idx] = 1.0f;

    __shared__ double sred[128];
    sred[threadIdx.x] = ssum;
    __syncthreads();
    for (int s = 64; s > 0; s >>= 1) {
        if (threadIdx.x < s) sred[threadIdx.x] += sred[threadIdx.x + s];
        __syncthreads();
    }
    if (threadIdx.x == 0) g_partial[blockIdx.x] = sred[0];
}

__global__ void k_loss(float* __restrict__ out) {
    __shared__ double sred[256];
    sred[threadIdx.x] = g_partial[threadIdx.x];
    __syncthreads();
    for (int s = 128; s > 0; s >>= 1) {
        if (threadIdx.x < s) sred[threadIdx.x] += sred[threadIdx.x + s];
        __syncthreads();
    }
    if (threadIdx.x == 0) {
        double m = sred[0] / (double)((long long)N_TOTAL * DIM);
        out[0] = (float)(m + 0.25 * m);
    }
}

extern "C" void kernel_launch(void* const* d_in, const int* in_sizes, int n_in,
                              void* d_out, int out_size) {
    const float* x = (const float*)d_in[0];
    const float* e = (const float*)d_in[1];
    if (n_in >= 2 && in_sizes[0] == KCODES * DIM && in_sizes[1] == N_TOTAL * DIM) {
        x = (const float*)d_in[1];
        e = (const float*)d_in[0];
    }
    float* out = (float*)d_out;

    cudaFuncSetAttribute(k_gemm, cudaFuncAttributeMaxDynamicSharedMemorySize, SMEM_BYTES);

    k_prep<<<KCODES / 128, 128>>>(e);

    long long encN = (long long)N_TOTAL * KCODES;
    k_zero_enc<<<1024, 256>>>(out + 1 + (size_t)N_TOTAL * DIM, encN);

    k_gemm<<<N_TOTAL / 128, 512, SMEM_BYTES>>>(x, e);
    k_out<<<N_TOTAL / 128, 128>>>(x, e, out);
    k_loss<<<1, 256>>>(out);
}

// round 12
// speedup vs baseline: 2.1168x; 1.0395x over previous
#include <cuda_runtime.h>
#include <cuda_bf16.h>
#include <math_constants.h>
#include <cstdint>

#define N_TOTAL 32768
#define DIM     256
#define KCODES  1024
#define HW      1024
#define MARGIN  2.5e-3f

// ---------------- scratch ----------------
__device__ __align__(16) uint32_t g_epack[(size_t)KCODES * 128];  // bf16x2 codes, K-major
__device__ float    g_embsq[KCODES];
__device__ int      g_idx[N_TOTAL];
__device__ double   g_partial[1024];

// ---------------- cp.async helpers ----------------
__device__ __forceinline__ void cp16(uint32_t saddr, const void* gaddr) {
    asm volatile("cp.async.cg.shared.global [%0], [%1], 16;" :: "r"(saddr), "l"(gaddr));
}
#define CP_COMMIT() asm volatile("cp.async.commit_group;" ::: "memory")
#define CP_WAIT(n)  asm volatile("cp.async.wait_group %0;" :: "n"(n) : "memory")

// order-preserving float -> u32; key = (ord(score) << 32) | idx  (min = best, ties -> min idx)
__device__ __forceinline__ unsigned long long mkkey(float s, int k) {
    unsigned u = __float_as_uint(s);
    u = (u & 0x80000000u) ? ~u : (u | 0x80000000u);
    return ((unsigned long long)u << 32) | (unsigned)k;
}

// ---------------- fused pack(e->bf16) + embsq (exact sequential order) ------
__global__ void k_prep(const float* __restrict__ e) {
    int k = blockIdx.x * blockDim.x + threadIdx.x;
    if (k >= KCODES) return;
    const float* p = e + (size_t)k * DIM;
    uint32_t* row = g_epack + (size_t)k * 128;
    float acc = 0.f;
#pragma unroll 8
    for (int cp = 0; cp < 128; cp++) {
        float f0 = p[2 * cp], f1 = p[2 * cp + 1];
        acc = __fadd_rn(acc, __fmul_rn(f0, f0));
        acc = __fadd_rn(acc, __fmul_rn(f1, f1));
        __nv_bfloat16 h0 = __float2bfloat16_rn(f0);
        __nv_bfloat16 h1 = __float2bfloat16_rn(f1);
        row[cp] = ((uint32_t)__bfloat16_as_ushort(h1) << 16) | __bfloat16_as_ushort(h0);
    }
    g_embsq[k] = acc;
}

// ---------------- fused: staging + rowsq + HMMA + argmin + exact rescore ----
#define SA_ST     132
#define SB_OFF    (128 * SA_ST)            // 16896
#define SB_BUF    (128 * SA_ST)
#define SBK_OFF   (SB_OFF + 2 * SB_BUF)    // 50688
#define SMINW_OFF (SBK_OFF + 1024)         // 51712
#define SBEST_OFF (SMINW_OFF + 512)        // 52224
#define SCNT_OFF  (SBEST_OFF + 128)        // 52352
#define SCAND_OFF (SCNT_OFF + 128)         // 52480
#define SAN_OFF   (SCAND_OFF + 1024)       // 53504
#define SKEY_OFF  (SAN_OFF + 128)          // 53632 (8B-aligned)
#define SOVF_OFF  (SKEY_OFF + 256)         // 53888 : [0]=count, [1..128]=rows
#define SMEM_U32  (SOVF_OFF + 132)         // 54020
#define SMEM_BYTES (SMEM_U32 * 4)          // 216080 B

__global__ __launch_bounds__(512, 1) void k_gemm(const float* __restrict__ x,
                                                 const float* __restrict__ e) {
    extern __shared__ __align__(16) uint32_t sm[];
    uint32_t* sA   = sm;
    float*    sBk  = (float*)(sm + SBK_OFF);
    float*    sMnW = (float*)(sm + SMINW_OFF);
    float*    sBest= (float*)(sm + SBEST_OFF);
    int*      sCnt = (int*)(sm + SCNT_OFF);
    unsigned short* sCand = (unsigned short*)(sm + SCAND_OFF);
    float*    sAn  = (float*)(sm + SAN_OFF);
    unsigned long long* sKey = (unsigned long long*)(sm + SKEY_OFF);
    int*      sOvf = (int*)(sm + SOVF_OFF);

    int tid = threadIdx.x;
    int lane = tid & 31, w = tid >> 5;
    int g = lane >> 2, tg = lane & 3;
    int wm = w & 3, wn = w >> 2;
    int n0 = blockIdx.x * 128;

    uint32_t smu;
    asm("{ .reg .u64 t; cvta.to.shared.u64 t, %1; cvt.u32.u64 %0, t; }"
        : "=r"(smu) : "l"(sm));

    // kick off panel 0 -> buf0
    {
        const uint32_t* gsrc = g_epack;
#pragma unroll
        for (int i = 0; i < 8; i++) {
            int seg = tid + i * 512, code = seg >> 5, j = seg & 31;
            cp16(smu + (uint32_t)(SB_OFF + code * SA_ST + j * 4) * 4,
                 gsrc + code * 128 + j * 4);
        }
        CP_COMMIT();
    }

    for (int i = tid; i < KCODES; i += 512) sBk[i] = g_embsq[i];
    if (tid < 128) { sCnt[tid] = 0; sBest[tid] = CUDART_INF_F; }
    if (tid == 0) sOvf[0] = 0;

    // ---- A staging + rowsq; sT aliased into B buffer 1 ----
    float* sT = (float*)(sm + SB_OFF + SB_BUF);
    int b = n0 >> 10, hw0 = n0 & 1023;
    const float* xb = x + (size_t)b * DIM * HW + hw0;
    float rs = 0.f;
    for (int cc0 = 0; cc0 < 8; cc0++) {
        __syncthreads();
#pragma unroll
        for (int i = 0; i < 8; i++) {
            int idx = tid + i * 512, ci = idx >> 7, nn = idx & 127;
            sT[ci * 129 + nn] = xb[(cc0 * 32 + ci) * HW + nn];
        }
        __syncthreads();
#pragma unroll
        for (int i = 0; i < 4; i++) {
            int idx = tid + i * 512, nn = idx >> 4, cp = idx & 15;
            float f0 = sT[(2 * cp) * 129 + nn];
            float f1 = sT[(2 * cp + 1) * 129 + nn];
            __nv_bfloat16 h0 = __float2bfloat16_rn(f0);
            __nv_bfloat16 h1 = __float2bfloat16_rn(f1);
            sA[nn * SA_ST + cc0 * 16 + cp] =
                ((uint32_t)__bfloat16_as_ushort(h1) << 16) | __bfloat16_as_ushort(h0);
        }
        if (tid < 128) {   // exact sequential rowsq
#pragma unroll
            for (int c = 0; c < 32; c++) {
                float v = sT[c * 129 + tid];
                rs = __fadd_rn(rs, __fmul_rn(v, v));
            }
        }
    }
    __syncthreads();
    if (tid < 128) sAn[tid] = rs;

    // panel 1 -> buf1
    {
        const uint32_t* gsrc = g_epack + (size_t)128 * 128;
#pragma unroll
        for (int i = 0; i < 8; i++) {
            int seg = tid + i * 512, code = seg >> 5, j = seg & 31;
            cp16(smu + (uint32_t)(SB_OFF + SB_BUF + code * SA_ST + j * 4) * 4,
                 gsrc + code * 128 + j * 4);
        }
        CP_COMMIT();
    }

    for (int p = 0; p < 8; p++) {
        if (p < 7) CP_WAIT(1); else CP_WAIT(0);
        __syncthreads();
        const uint32_t* Bbuf = sm + SB_OFF + (p & 1) * SB_BUF;

        float acc[2][4][4];
#pragma unroll
        for (int mt = 0; mt < 2; mt++)
#pragma unroll
            for (int nt = 0; nt < 4; nt++)
#pragma unroll
                for (int e2 = 0; e2 < 4; e2++) acc[mt][nt][e2] = 0.f;

        const uint32_t* Ab = sA + (wm * 32 + g) * SA_ST;
        const uint32_t* Bb = Bbuf + (wn * 32 + g) * SA_ST;
#pragma unroll
        for (int ks = 0; ks < 16; ks++) {
            uint32_t a[2][4];
#pragma unroll
            for (int mt = 0; mt < 2; mt++) {
                const uint32_t* ap = Ab + mt * 16 * SA_ST + ks * 8 + tg;
                a[mt][0] = ap[0];
                a[mt][1] = ap[8 * SA_ST];
                a[mt][2] = ap[4];
                a[mt][3] = ap[8 * SA_ST + 4];
            }
#pragma unroll
            for (int nt = 0; nt < 4; nt++) {
                uint32_t b0 = Bb[nt * 8 * SA_ST + ks * 8 + tg];
                uint32_t b1 = Bb[nt * 8 * SA_ST + ks * 8 + tg + 4];
#pragma unroll
                for (int mt = 0; mt < 2; mt++) {
                    asm volatile(
                        "mma.sync.aligned.m16n8k16.row.col.f32.bf16.bf16.f32 "
                        "{%0,%1,%2,%3}, {%4,%5,%6,%7}, {%8,%9}, {%0,%1,%2,%3};"
                        : "+f"(acc[mt][nt][0]), "+f"(acc[mt][nt][1]),
                          "+f"(acc[mt][nt][2]), "+f"(acc[mt][nt][3])
                        : "r"(a[mt][0]), "r"(a[mt][1]), "r"(a[mt][2]), "r"(a[mt][3]),
                          "r"(b0), "r"(b1));
                }
            }
        }

        // ---- phase 1: per-(row,warp) min ----
        int kb = p * 128 + wn * 32 + 2 * tg;
        float bkv[4][2];
#pragma unroll
        for (int nt = 0; nt < 4; nt++) {
            bkv[nt][0] = sBk[kb + nt * 8];
            bkv[nt][1] = sBk[kb + nt * 8 + 1];
        }
        float mn[4] = {CUDART_INF_F, CUDART_INF_F, CUDART_INF_F, CUDART_INF_F};
#pragma unroll
        for (int mt = 0; mt < 2; mt++)
#pragma unroll
            for (int nt = 0; nt < 4; nt++) {
                float t0 = __fmaf_rn(-2.f, acc[mt][nt][0], bkv[nt][0]);
                float t1 = __fmaf_rn(-2.f, acc[mt][nt][1], bkv[nt][1]);
                float t2 = __fmaf_rn(-2.f, acc[mt][nt][2], bkv[nt][0]);
                float t3 = __fmaf_rn(-2.f, acc[mt][nt][3], bkv[nt][1]);
                mn[mt * 2]     = fminf(mn[mt * 2], fminf(t0, t1));
                mn[mt * 2 + 1] = fminf(mn[mt * 2 + 1], fminf(t2, t3));
            }
#pragma unroll
        for (int i = 0; i < 4; i++) {
            mn[i] = fminf(mn[i], __shfl_xor_sync(0xffffffffu, mn[i], 1));
            mn[i] = fminf(mn[i], __shfl_xor_sync(0xffffffffu, mn[i], 2));
        }
        if (tg == 0) {
#pragma unroll
            for (int mt = 0; mt < 2; mt++)
#pragma unroll
                for (int h = 0; h < 2; h++) {
                    int r = wm * 32 + mt * 16 + g + 8 * h;
                    sMnW[r * 4 + wn] = mn[mt * 2 + h];
                }
        }
        __syncthreads();

        // prefetch panel p+2
        if (p + 2 < 8) {
            const uint32_t* gsrc = g_epack + (size_t)(p + 2) * 128 * 128;
            uint32_t dst = smu + (uint32_t)(SB_OFF + (p & 1) * SB_BUF) * 4;
#pragma unroll
            for (int i = 0; i < 8; i++) {
                int seg = tid + i * 512, code = seg >> 5, j = seg & 31;
                cp16(dst + (uint32_t)(code * SA_ST + j * 4) * 4,
                     gsrc + code * 128 + j * 4);
            }
            CP_COMMIT();
        }

        // ---- phase 2: capture candidates vs global running best ----
        float thr[4];
#pragma unroll
        for (int mt = 0; mt < 2; mt++)
#pragma unroll
            for (int h = 0; h < 2; h++) {
                int r = wm * 32 + mt * 16 + g + 8 * h;
                float t4 = fminf(fminf(sMnW[r * 4 + 0], sMnW[r * 4 + 1]),
                                 fminf(sMnW[r * 4 + 2], sMnW[r * 4 + 3]));
                thr[mt * 2 + h] = fminf(sBest[r], t4);
            }
#pragma unroll
        for (int mt = 0; mt < 2; mt++)
#pragma unroll
            for (int nt = 0; nt < 4; nt++)
#pragma unroll
                for (int e2 = 0; e2 < 4; e2++) {
                    float t = __fmaf_rn(-2.f, acc[mt][nt][e2], bkv[nt][e2 & 1]);
                    int h = e2 >> 1;
                    if (t <= thr[mt * 2 + h] + MARGIN) {
                        int r = wm * 32 + mt * 16 + g + 8 * h;
                        int k = kb + nt * 8 + (e2 & 1);
                        int pos = atomicAdd(&sCnt[r], 1);
                        if (pos < 16) sCand[r * 16 + pos] = (unsigned short)k;
                    }
                }
        __syncthreads();
        if (wn == 0 && tg == 0) {
#pragma unroll
            for (int mt = 0; mt < 2; mt++)
#pragma unroll
                for (int h = 0; h < 2; h++) {
                    int r = wm * 32 + mt * 16 + g + 8 * h;
                    sBest[r] = thr[mt * 2 + h];
                }
        }
    }
    __syncthreads();

    // ---- in-block exact rescore (R4's bit-exact chain) ----
    if (tid < 128) sKey[tid] = 0xFFFFFFFFFFFFFFFFull;
    __syncthreads();

    int rr = tid & 127, slot = tid >> 7;   // 4 slots per row
    int cnt = sCnt[rr];
    const float* xpr = x + (size_t)b * DIM * HW + hw0 + rr;
    if (cnt <= 16) {
        float an = sAn[rr];
        for (int s = slot; s < cnt; s += 4) {
            int k = sCand[rr * 16 + s];
            const float* ep = e + (size_t)k * DIM;
            float a = 0.f;
#pragma unroll 4
            for (int d = 0; d < DIM; d++)
                a = __fmaf_rn(xpr[d * HW], ep[d], a);
            float sc = __fsub_rn(__fadd_rn(an, sBk[k]), __fmul_rn(2.0f, a));
            atomicMin(&sKey[rr], mkkey(sc, k));
        }
    } else if (slot == 0) {
        int pidx = atomicAdd(&sOvf[0], 1);
        sOvf[1 + pidx] = rr;
    }
    __syncthreads();

    // overflow rows: one warp per row, full 1024-code exact scan
    int novf = sOvf[0];
    for (int li = w; li < novf; li += 16) {
        int r2 = sOvf[1 + li];
        const float* xp2 = x + (size_t)b * DIM * HW + hw0 + r2;
        float an2 = sAn[r2];
        unsigned long long bk = 0xFFFFFFFFFFFFFFFFull;
        for (int k = lane; k < KCODES; k += 32) {
            const float* ep = e + (size_t)k * DIM;
            float a = 0.f;
#pragma unroll 4
            for (int d = 0; d < DIM; d++)
                a = __fmaf_rn(xp2[d * HW], ep[d], a);
            float sc = __fsub_rn(__fadd_rn(an2, sBk[k]), __fmul_rn(2.0f, a));
            unsigned long long kk = mkkey(sc, k);
            if (kk < bk) bk = kk;
        }
#pragma unroll
        for (int m = 16; m > 0; m >>= 1) {
            unsigned long long o = __shfl_xor_sync(0xffffffffu, bk, m);
            if (o < bk) bk = o;
        }
        if (lane == 0) sKey[r2] = bk;
    }
    __syncthreads();
    if (tid < 128) g_idx[n0 + tid] = (int)(sKey[tid] & 0xFFFFFFFFu);
}

// ---------------- fused outputs: quantized_st + one-hot encodings + loss ----
// 1024 blocks x 256 threads. Thread = (sub 0..7, rowl 0..31): row n = blk*32+rowl,
// c in [sub*32, sub*32+32), encodings segment [sub*128, sub*128+128).
__global__ __launch_bounds__(256) void k_out(const float* __restrict__ x,
                                             const float* __restrict__ emb,
                                             float* __restrict__ out) {
    int rowl = threadIdx.x & 31, sub = threadIdx.x >> 5;
    int n = blockIdx.x * 32 + rowl;
    int b = n >> 10, hw = n & 1023;
    const float* xp = x + (size_t)b * DIM * HW + hw;
    float* qp = out + 1 + (size_t)b * DIM * HW + hw;
    int idx = g_idx[n];
    const float* ep = emb + (size_t)idx * DIM;
    double ssum = 0.0;
    int c0 = sub * 32;
#pragma unroll 4
    for (int i = 0; i < 32; i++) {
        int c = c0 + i;
        float in = xp[c * HW];
        float q  = ep[c];
        float d  = __fsub_rn(q, in);          // fl(q - in)
        float st = __fadd_rn(in, d);          // fl(in + d)
        qp[c * HW] = st;
        ssum += (double)__fmul_rn(d, d);
    }

    // one-hot segment: 128 floats at global float index 8388609 + n*1024 + sub*128
    // byte alignment is always ≡4 (mod 16): 3 scalars + 31 uint4 + 1 scalar.
    float* seg = out + 1 + (size_t)N_TOTAL * DIM + (size_t)n * KCODES + sub * 128;
    seg[0] = 0.f; seg[1] = 0.f; seg[2] = 0.f;
    uint4* v4 = (uint4*)(seg + 3);
#pragma unroll
    for (int i = 0; i < 31; i++) v4[i] = make_uint4(0, 0, 0, 0);
    seg[127] = 0.f;
    int rel = idx - sub * 128;
    if (rel >= 0 && rel < 128) seg[rel] = 1.0f;

    __shared__ double sred[256];
    sred[threadIdx.x] = ssum;
    __syncthreads();
    for (int s = 128; s > 0; s >>= 1) {
        if (threadIdx.x < s) sred[threadIdx.x] += sred[threadIdx.x + s];
        __syncthreads();
    }
    if (threadIdx.x == 0) g_partial[blockIdx.x] = sred[0];
}

__global__ void k_loss(float* __restrict__ out) {
    __shared__ double sred[256];
    double a = 0.0;
#pragma unroll
    for (int i = 0; i < 4; i++) a += g_partial[threadIdx.x * 4 + i];
    sred[threadIdx.x] = a;
    __syncthreads();
    for (int s = 128; s > 0; s >>= 1) {
        if (threadIdx.x < s) sred[threadIdx.x] += sred[threadIdx.x + s];
        __syncthreads();
    }
    if (threadIdx.x == 0) {
        double m = sred[0] / (double)((long long)N_TOTAL * DIM);
        out[0] = (float)(m + 0.25 * m);
    }
}

extern "C" void kernel_launch(void* const* d_in, const int* in_sizes, int n_in,
                              void* d_out, int out_size) {
    const float* x = (const float*)d_in[0];
    const float* e = (const float*)d_in[1];
    if (n_in >= 2 && in_sizes[0] == KCODES * DIM && in_sizes[1] == N_TOTAL * DIM) {
        x = (const float*)d_in[1];
        e = (const float*)d_in[0];
    }
    float* out = (float*)d_out;

    cudaFuncSetAttribute(k_gemm, cudaFuncAttributeMaxDynamicSharedMemorySize, SMEM_BYTES);

    k_prep<<<32, 32>>>(e);
    k_gemm<<<N_TOTAL / 128, 512, SMEM_BYTES>>>(x, e);
    k_out<<<N_TOTAL / 32, 256>>>(x, e, out);
    k_loss<<<1, 256>>>(out);
}

// round 13
// speedup vs baseline: 2.3353x; 1.1032x over previous
#include <cuda_runtime.h>
#include <cuda_bf16.h>
#include <math_constants.h>
#include <cstdint>

#define N_TOTAL 32768
#define DIM     256
#define KCODES  1024
#define HW      1024
#define MARGIN  2.5e-3f

// ---------------- scratch ----------------
__device__ __align__(16) uint32_t g_epack[(size_t)KCODES * 128];  // bf16x2 codes, K-major
__device__ float    g_embsq[KCODES];
__device__ int      g_idx[N_TOTAL];
__device__ double   g_partial[1024];

// ---------------- cp.async helpers ----------------
__device__ __forceinline__ void cp16(uint32_t saddr, const void* gaddr) {
    asm volatile("cp.async.cg.shared.global [%0], [%1], 16;" :: "r"(saddr), "l"(gaddr));
}
#define CP_COMMIT() asm volatile("cp.async.commit_group;" ::: "memory")
#define CP_WAIT(n)  asm volatile("cp.async.wait_group %0;" :: "n"(n) : "memory")

// order-preserving float -> u32; key = (ord(score) << 32) | idx  (min = best, ties -> min idx)
__device__ __forceinline__ unsigned long long mkkey(float s, int k) {
    unsigned u = __float_as_uint(s);
    u = (u & 0x80000000u) ? ~u : (u | 0x80000000u);
    return ((unsigned long long)u << 32) | (unsigned)k;
}

// ---------------- fused pack(e->bf16) + embsq (exact sequential order) ------
__global__ void k_prep(const float* __restrict__ e) {
    int k = blockIdx.x * blockDim.x + threadIdx.x;
    if (k >= KCODES) return;
    const float* p = e + (size_t)k * DIM;
    uint32_t* row = g_epack + (size_t)k * 128;
    float acc = 0.f;
#pragma unroll 8
    for (int cp = 0; cp < 128; cp++) {
        float f0 = p[2 * cp], f1 = p[2 * cp + 1];
        acc = __fadd_rn(acc, __fmul_rn(f0, f0));
        acc = __fadd_rn(acc, __fmul_rn(f1, f1));
        __nv_bfloat16 h0 = __float2bfloat16_rn(f0);
        __nv_bfloat16 h1 = __float2bfloat16_rn(f1);
        row[cp] = ((uint32_t)__bfloat16_as_ushort(h1) << 16) | __bfloat16_as_ushort(h0);
    }
    g_embsq[k] = acc;
}

// ---------------- fused: staging + rowsq + HMMA + argmin + exact rescore ----
#define SA_ST     132
#define SB_OFF    (128 * SA_ST)            // 16896
#define SB_BUF    (128 * SA_ST)
#define SBK_OFF   (SB_OFF + 2 * SB_BUF)    // 50688
#define SMINW_OFF (SBK_OFF + 1024)         // 51712
#define SBEST_OFF (SMINW_OFF + 512)        // 52224
#define SCNT_OFF  (SBEST_OFF + 128)        // 52352
#define SCAND_OFF (SCNT_OFF + 128)         // 52480
#define SAN_OFF   (SCAND_OFF + 1024)       // 53504
#define SKEY_OFF  (SAN_OFF + 128)          // 53632 (8B-aligned)
#define SOVF_OFF  (SKEY_OFF + 256)         // 53888 : [0]=count, [1..128]=rows
#define SMEM_U32  (SOVF_OFF + 132)         // 54020
#define SMEM_BYTES (SMEM_U32 * 4)          // 216080 B

__global__ __launch_bounds__(512, 1) void k_gemm(const float* __restrict__ x,
                                                 const float* __restrict__ e) {
    extern __shared__ __align__(16) uint32_t sm[];
    uint32_t* sA   = sm;
    float*    sBk  = (float*)(sm + SBK_OFF);
    float*    sMnW = (float*)(sm + SMINW_OFF);
    float*    sBest= (float*)(sm + SBEST_OFF);
    int*      sCnt = (int*)(sm + SCNT_OFF);
    unsigned short* sCand = (unsigned short*)(sm + SCAND_OFF);
    float*    sAn  = (float*)(sm + SAN_OFF);
    unsigned long long* sKey = (unsigned long long*)(sm + SKEY_OFF);
    int*      sOvf = (int*)(sm + SOVF_OFF);

    int tid = threadIdx.x;
    int lane = tid & 31, w = tid >> 5;
    int g = lane >> 2, tg = lane & 3;
    int wm = w & 3, wn = w >> 2;
    int n0 = blockIdx.x * 128;

    uint32_t smu;
    asm("{ .reg .u64 t; cvta.to.shared.u64 t, %1; cvt.u32.u64 %0, t; }"
        : "=r"(smu) : "l"(sm));

    // kick off panel 0 -> buf0
    {
        const uint32_t* gsrc = g_epack;
#pragma unroll
        for (int i = 0; i < 8; i++) {
            int seg = tid + i * 512, code = seg >> 5, j = seg & 31;
            cp16(smu + (uint32_t)(SB_OFF + code * SA_ST + j * 4) * 4,
                 gsrc + code * 128 + j * 4);
        }
        CP_COMMIT();
    }

    for (int i = tid; i < KCODES; i += 512) sBk[i] = g_embsq[i];
    if (tid < 128) { sCnt[tid] = 0; sBest[tid] = CUDART_INF_F; }
    if (tid == 0) sOvf[0] = 0;

    // ---- A staging + rowsq; sT aliased into B buffer 1 ----
    float* sT = (float*)(sm + SB_OFF + SB_BUF);
    int b = n0 >> 10, hw0 = n0 & 1023;
    const float* xb = x + (size_t)b * DIM * HW + hw0;
    float rs = 0.f;
    for (int cc0 = 0; cc0 < 8; cc0++) {
        __syncthreads();
#pragma unroll
        for (int i = 0; i < 8; i++) {
            int idx = tid + i * 512, ci = idx >> 7, nn = idx & 127;
            sT[ci * 129 + nn] = xb[(cc0 * 32 + ci) * HW + nn];
        }
        __syncthreads();
#pragma unroll
        for (int i = 0; i < 4; i++) {
            int idx = tid + i * 512, nn = idx >> 4, cp = idx & 15;
            float f0 = sT[(2 * cp) * 129 + nn];
            float f1 = sT[(2 * cp + 1) * 129 + nn];
            __nv_bfloat16 h0 = __float2bfloat16_rn(f0);
            __nv_bfloat16 h1 = __float2bfloat16_rn(f1);
            sA[nn * SA_ST + cc0 * 16 + cp] =
                ((uint32_t)__bfloat16_as_ushort(h1) << 16) | __bfloat16_as_ushort(h0);
        }
        if (tid < 128) {   // exact sequential rowsq
#pragma unroll
            for (int c = 0; c < 32; c++) {
                float v = sT[c * 129 + tid];
                rs = __fadd_rn(rs, __fmul_rn(v, v));
            }
        }
    }
    __syncthreads();
    if (tid < 128) sAn[tid] = rs;

    // panel 1 -> buf1
    {
        const uint32_t* gsrc = g_epack + (size_t)128 * 128;
#pragma unroll
        for (int i = 0; i < 8; i++) {
            int seg = tid + i * 512, code = seg >> 5, j = seg & 31;
            cp16(smu + (uint32_t)(SB_OFF + SB_BUF + code * SA_ST + j * 4) * 4,
                 gsrc + code * 128 + j * 4);
        }
        CP_COMMIT();
    }

    for (int p = 0; p < 8; p++) {
        if (p < 7) CP_WAIT(1); else CP_WAIT(0);
        __syncthreads();
        const uint32_t* Bbuf = sm + SB_OFF + (p & 1) * SB_BUF;

        float acc[2][4][4];
#pragma unroll
        for (int mt = 0; mt < 2; mt++)
#pragma unroll
            for (int nt = 0; nt < 4; nt++)
#pragma unroll
                for (int e2 = 0; e2 < 4; e2++) acc[mt][nt][e2] = 0.f;

        const uint32_t* Ab = sA + (wm * 32 + g) * SA_ST;
        const uint32_t* Bb = Bbuf + (wn * 32 + g) * SA_ST;
#pragma unroll
        for (int ks = 0; ks < 16; ks++) {
            uint32_t a[2][4];
#pragma unroll
            for (int mt = 0; mt < 2; mt++) {
                const uint32_t* ap = Ab + mt * 16 * SA_ST + ks * 8 + tg;
                a[mt][0] = ap[0];
                a[mt][1] = ap[8 * SA_ST];
                a[mt][2] = ap[4];
                a[mt][3] = ap[8 * SA_ST + 4];
            }
#pragma unroll
            for (int nt = 0; nt < 4; nt++) {
                uint32_t b0 = Bb[nt * 8 * SA_ST + ks * 8 + tg];
                uint32_t b1 = Bb[nt * 8 * SA_ST + ks * 8 + tg + 4];
#pragma unroll
                for (int mt = 0; mt < 2; mt++) {
                    asm volatile(
                        "mma.sync.aligned.m16n8k16.row.col.f32.bf16.bf16.f32 "
                        "{%0,%1,%2,%3}, {%4,%5,%6,%7}, {%8,%9}, {%0,%1,%2,%3};"
                        : "+f"(acc[mt][nt][0]), "+f"(acc[mt][nt][1]),
                          "+f"(acc[mt][nt][2]), "+f"(acc[mt][nt][3])
                        : "r"(a[mt][0]), "r"(a[mt][1]), "r"(a[mt][2]), "r"(a[mt][3]),
                          "r"(b0), "r"(b1));
                }
            }
        }

        // ---- phase 1: per-(row,warp) min ----
        int kb = p * 128 + wn * 32 + 2 * tg;
        float bkv[4][2];
#pragma unroll
        for (int nt = 0; nt < 4; nt++) {
            bkv[nt][0] = sBk[kb + nt * 8];
            bkv[nt][1] = sBk[kb + nt * 8 + 1];
        }
        float mn[4] = {CUDART_INF_F, CUDART_INF_F, CUDART_INF_F, CUDART_INF_F};
#pragma unroll
        for (int mt = 0; mt < 2; mt++)
#pragma unroll
            for (int nt = 0; nt < 4; nt++) {
                float t0 = __fmaf_rn(-2.f, acc[mt][nt][0], bkv[nt][0]);
                float t1 = __fmaf_rn(-2.f, acc[mt][nt][1], bkv[nt][1]);
                float t2 = __fmaf_rn(-2.f, acc[mt][nt][2], bkv[nt][0]);
                float t3 = __fmaf_rn(-2.f, acc[mt][nt][3], bkv[nt][1]);
                mn[mt * 2]     = fminf(mn[mt * 2], fminf(t0, t1));
                mn[mt * 2 + 1] = fminf(mn[mt * 2 + 1], fminf(t2, t3));
            }
#pragma unroll
        for (int i = 0; i < 4; i++) {
            mn[i] = fminf(mn[i], __shfl_xor_sync(0xffffffffu, mn[i], 1));
            mn[i] = fminf(mn[i], __shfl_xor_sync(0xffffffffu, mn[i], 2));
        }
        if (tg == 0) {
#pragma unroll
            for (int mt = 0; mt < 2; mt++)
#pragma unroll
                for (int h = 0; h < 2; h++) {
                    int r = wm * 32 + mt * 16 + g + 8 * h;
                    sMnW[r * 4 + wn] = mn[mt * 2 + h];
                }
        }
        __syncthreads();

        // prefetch panel p+2
        if (p + 2 < 8) {
            const uint32_t* gsrc = g_epack + (size_t)(p + 2) * 128 * 128;
            uint32_t dst = smu + (uint32_t)(SB_OFF + (p & 1) * SB_BUF) * 4;
#pragma unroll
            for (int i = 0; i < 8; i++) {
                int seg = tid + i * 512, code = seg >> 5, j = seg & 31;
                cp16(dst + (uint32_t)(code * SA_ST + j * 4) * 4,
                     gsrc + code * 128 + j * 4);
            }
            CP_COMMIT();
        }

        // ---- phase 2: capture candidates vs global running best ----
        float thr[4];
#pragma unroll
        for (int mt = 0; mt < 2; mt++)
#pragma unroll
            for (int h = 0; h < 2; h++) {
                int r = wm * 32 + mt * 16 + g + 8 * h;
                float t4 = fminf(fminf(sMnW[r * 4 + 0], sMnW[r * 4 + 1]),
                                 fminf(sMnW[r * 4 + 2], sMnW[r * 4 + 3]));
                thr[mt * 2 + h] = fminf(sBest[r], t4);
            }
#pragma unroll
        for (int mt = 0; mt < 2; mt++)
#pragma unroll
            for (int nt = 0; nt < 4; nt++)
#pragma unroll
                for (int e2 = 0; e2 < 4; e2++) {
                    float t = __fmaf_rn(-2.f, acc[mt][nt][e2], bkv[nt][e2 & 1]);
                    int h = e2 >> 1;
                    if (t <= thr[mt * 2 + h] + MARGIN) {
                        int r = wm * 32 + mt * 16 + g + 8 * h;
                        int k = kb + nt * 8 + (e2 & 1);
                        int pos = atomicAdd(&sCnt[r], 1);
                        if (pos < 16) sCand[r * 16 + pos] = (unsigned short)k;
                    }
                }
        __syncthreads();
        if (wn == 0 && tg == 0) {
#pragma unroll
            for (int mt = 0; mt < 2; mt++)
#pragma unroll
                for (int h = 0; h < 2; h++) {
                    int r = wm * 32 + mt * 16 + g + 8 * h;
                    sBest[r] = thr[mt * 2 + h];
                }
        }
    }
    __syncthreads();

    // ---- in-block exact rescore (R4's bit-exact chain) ----
    if (tid < 128) sKey[tid] = 0xFFFFFFFFFFFFFFFFull;
    __syncthreads();

    int rr = tid & 127, slot = tid >> 7;   // 4 slots per row
    int cnt = sCnt[rr];
    const float* xpr = x + (size_t)b * DIM * HW + hw0 + rr;
    if (cnt <= 16) {
        float an = sAn[rr];
        for (int s = slot; s < cnt; s += 4) {
            int k = sCand[rr * 16 + s];
            const float* ep = e + (size_t)k * DIM;
            float a = 0.f;
#pragma unroll 4
            for (int d = 0; d < DIM; d++)
                a = __fmaf_rn(xpr[d * HW], ep[d], a);
            float sc = __fsub_rn(__fadd_rn(an, sBk[k]), __fmul_rn(2.0f, a));
            atomicMin(&sKey[rr], mkkey(sc, k));
        }
    } else if (slot == 0) {
        int pidx = atomicAdd(&sOvf[0], 1);
        sOvf[1 + pidx] = rr;
    }
    __syncthreads();

    // overflow rows: one warp per row, full 1024-code exact scan
    int novf = sOvf[0];
    for (int li = w; li < novf; li += 16) {
        int r2 = sOvf[1 + li];
        const float* xp2 = x + (size_t)b * DIM * HW + hw0 + r2;
        float an2 = sAn[r2];
        unsigned long long bk = 0xFFFFFFFFFFFFFFFFull;
        for (int k = lane; k < KCODES; k += 32) {
            const float* ep = e + (size_t)k * DIM;
            float a = 0.f;
#pragma unroll 4
            for (int d = 0; d < DIM; d++)
                a = __fmaf_rn(xp2[d * HW], ep[d], a);
            float sc = __fsub_rn(__fadd_rn(an2, sBk[k]), __fmul_rn(2.0f, a));
            unsigned long long kk = mkkey(sc, k);
            if (kk < bk) bk = kk;
        }
#pragma unroll
        for (int m = 16; m > 0; m >>= 1) {
            unsigned long long o = __shfl_xor_sync(0xffffffffu, bk, m);
            if (o < bk) bk = o;
        }
        if (lane == 0) sKey[r2] = bk;
    }
    __syncthreads();
    if (tid < 128) g_idx[n0 + tid] = (int)(sKey[tid] & 0xFFFFFFFFu);
}

// ---------------- fused outputs: quantized_st + one-hot encodings + loss ----
// 1024 blocks x 256 threads (32 rows per block).
// Phase A (quantized+loss): thread (sub,rowl) — lanes sweep rows -> coalesced.
// Phase B (encodings): warp-per-row — lanes sweep columns -> coalesced.
__global__ __launch_bounds__(256) void k_out(const float* __restrict__ x,
                                             const float* __restrict__ emb,
                                             float* __restrict__ out) {
    int rowl = threadIdx.x & 31, sub = threadIdx.x >> 5;
    int n = blockIdx.x * 32 + rowl;
    int b = n >> 10, hw = n & 1023;
    const float* xp = x + (size_t)b * DIM * HW + hw;
    float* qp = out + 1 + (size_t)b * DIM * HW + hw;
    int idx = g_idx[n];
    const float* ep = emb + (size_t)idx * DIM;
    double ssum = 0.0;
    int c0 = sub * 32;
#pragma unroll 4
    for (int i = 0; i < 32; i++) {
        int c = c0 + i;
        float in = xp[c * HW];
        float q  = ep[c];
        float d  = __fsub_rn(q, in);          // fl(q - in)
        float st = __fadd_rn(in, d);          // fl(in + d)
        qp[c * HW] = st;
        ssum += (double)__fmul_rn(d, d);
    }

    // ---- Phase B: one-hot encodings, warp-per-row coalesced ----
    // warp `sub` handles 4 rows; per row: 1024 floats at base ≡4 (mod 16):
    // 3 scalar head + 255 uint4 + 1 scalar tail, then lane 0 writes the 1.0.
    int lane = rowl;
#pragma unroll
    for (int rr = 0; rr < 4; rr++) {
        int n2 = blockIdx.x * 32 + sub * 4 + rr;
        int idx2 = g_idx[n2];
        float* seg = out + 1 + (size_t)N_TOTAL * DIM + (size_t)n2 * KCODES;
        if (lane < 3) seg[lane] = 0.f;
        if (lane == 3) seg[1023] = 0.f;
        uint4* v4 = (uint4*)(seg + 3);
#pragma unroll
        for (int it = 0; it < 8; it++) {
            int i = it * 32 + lane;
            if (i < 255) v4[i] = make_uint4(0, 0, 0, 0);
        }
        __syncwarp();
        if (lane == 0) seg[idx2] = 1.0f;
    }

    __shared__ double sred[256];
    sred[threadIdx.x] = ssum;
    __syncthreads();
    for (int s = 128; s > 0; s >>= 1) {
        if (threadIdx.x < s) sred[threadIdx.x] += sred[threadIdx.x + s];
        __syncthreads();
    }
    if (threadIdx.x == 0) g_partial[blockIdx.x] = sred[0];
}

__global__ void k_loss(float* __restrict__ out) {
    __shared__ double sred[256];
    double a = 0.0;
#pragma unroll
    for (int i = 0; i < 4; i++) a += g_partial[threadIdx.x * 4 + i];
    sred[threadIdx.x] = a;
    __syncthreads();
    for (int s = 128; s > 0; s >>= 1) {
        if (threadIdx.x < s) sred[threadIdx.x] += sred[threadIdx.x + s];
        __syncthreads();
    }
    if (threadIdx.x == 0) {
        double m = sred[0] / (double)((long long)N_TOTAL * DIM);
        out[0] = (float)(m + 0.25 * m);
    }
}

extern "C" void kernel_launch(void* const* d_in, const int* in_sizes, int n_in,
                              void* d_out, int out_size) {
    const float* x = (const float*)d_in[0];
    const float* e = (const float*)d_in[1];
    if (n_in >= 2 && in_sizes[0] == KCODES * DIM && in_sizes[1] == N_TOTAL * DIM) {
        x = (const float*)d_in[1];
        e = (const float*)d_in[0];
    }
    float* out = (float*)d_out;

    cudaFuncSetAttribute(k_gemm, cudaFuncAttributeMaxDynamicSharedMemorySize, SMEM_BYTES);

    k_prep<<<32, 32>>>(e);
    k_gemm<<<N_TOTAL / 128, 512, SMEM_BYTES>>>(x, e);
    k_out<<<N_TOTAL / 32, 256>>>(x, e, out);
    k_loss<<<1, 256>>>(out);
}

// round 14
// speedup vs baseline: 2.3362x; 1.0004x over previous
#include <cuda_runtime.h>
#include <cuda_bf16.h>
#include <math_constants.h>
#include <cstdint>

#define N_TOTAL 32768
#define DIM     256
#define KCODES  1024
#define HW      1024
#define MARGIN  2.5e-3f
#define CANDCAP 32

// ---------------- scratch ----------------
__device__ __align__(16) uint32_t g_epack[(size_t)KCODES * 128];  // bf16x2 codes, K-major
__device__ float    g_embsq[KCODES];
__device__ int      g_idx[N_TOTAL];
__device__ double   g_partial[1024];

// ---------------- cp.async helpers ----------------
__device__ __forceinline__ void cp16(uint32_t saddr, const void* gaddr) {
    asm volatile("cp.async.cg.shared.global [%0], [%1], 16;" :: "r"(saddr), "l"(gaddr));
}
#define CP_COMMIT() asm volatile("cp.async.commit_group;" ::: "memory")
#define CP_WAIT(n)  asm volatile("cp.async.wait_group %0;" :: "n"(n) : "memory")

// order-preserving float -> u32; key = (ord(score) << 32) | idx  (min = best, ties -> min idx)
__device__ __forceinline__ unsigned long long mkkey(float s, int k) {
    unsigned u = __float_as_uint(s);
    u = (u & 0x80000000u) ? ~u : (u | 0x80000000u);
    return ((unsigned long long)u << 32) | (unsigned)k;
}

// ---------------- fused pack(e->bf16) + embsq (exact sequential order) ------
__global__ void k_prep(const float* __restrict__ e) {
    int k = blockIdx.x * blockDim.x + threadIdx.x;
    if (k >= KCODES) return;
    const float* p = e + (size_t)k * DIM;
    uint32_t* row = g_epack + (size_t)k * 128;
    float acc = 0.f;
#pragma unroll 8
    for (int cp = 0; cp < 128; cp++) {
        float f0 = p[2 * cp], f1 = p[2 * cp + 1];
        acc = __fadd_rn(acc, __fmul_rn(f0, f0));
        acc = __fadd_rn(acc, __fmul_rn(f1, f1));
        __nv_bfloat16 h0 = __float2bfloat16_rn(f0);
        __nv_bfloat16 h1 = __float2bfloat16_rn(f1);
        row[cp] = ((uint32_t)__bfloat16_as_ushort(h1) << 16) | __bfloat16_as_ushort(h0);
    }
    g_embsq[k] = acc;
}

// ---------------- fused: staging + rowsq + HMMA + argmin + exact rescore ----
#define SA_ST     132
#define SB_OFF    (128 * SA_ST)            // 16896
#define SB_BUF    (128 * SA_ST)
#define SBK_OFF   (SB_OFF + 2 * SB_BUF)    // 50688
#define SMINW_OFF (SBK_OFF + 1024)         // 51712
#define SBEST_OFF (SMINW_OFF + 512)        // 52224
#define SCNT_OFF  (SBEST_OFF + 128)        // 52352
#define SCAND_OFF (SCNT_OFF + 128)         // 52480 : u16 [128][32] = 2048 u32
#define SAN_OFF   (SCAND_OFF + 2048)       // 54528
#define SKEY_OFF  (SAN_OFF + 128)          // 54656 (8B-aligned)
#define SOVF_OFF  (SKEY_OFF + 256)         // 54912 : [0]=count, [1..128]=rows
#define SMEM_U32  (SOVF_OFF + 132)         // 55044
#define SMEM_BYTES (SMEM_U32 * 4)          // 220176 B < 227KB opt-in

__global__ __launch_bounds__(512, 1) void k_gemm(const float* __restrict__ x,
                                                 const float* __restrict__ e) {
    extern __shared__ __align__(16) uint32_t sm[];
    uint32_t* sA   = sm;
    float*    sBk  = (float*)(sm + SBK_OFF);
    float*    sMnW = (float*)(sm + SMINW_OFF);
    float*    sBest= (float*)(sm + SBEST_OFF);
    int*      sCnt = (int*)(sm + SCNT_OFF);
    unsigned short* sCand = (unsigned short*)(sm + SCAND_OFF);
    float*    sAn  = (float*)(sm + SAN_OFF);
    unsigned long long* sKey = (unsigned long long*)(sm + SKEY_OFF);
    int*      sOvf = (int*)(sm + SOVF_OFF);

    int tid = threadIdx.x;
    int lane = tid & 31, w = tid >> 5;
    int g = lane >> 2, tg = lane & 3;
    int wm = w & 3, wn = w >> 2;
    int n0 = blockIdx.x * 128;

    uint32_t smu;
    asm("{ .reg .u64 t; cvta.to.shared.u64 t, %1; cvt.u32.u64 %0, t; }"
        : "=r"(smu) : "l"(sm));

    // kick off panel 0 -> buf0
    {
        const uint32_t* gsrc = g_epack;
#pragma unroll
        for (int i = 0; i < 8; i++) {
            int seg = tid + i * 512, code = seg >> 5, j = seg & 31;
            cp16(smu + (uint32_t)(SB_OFF + code * SA_ST + j * 4) * 4,
                 gsrc + code * 128 + j * 4);
        }
        CP_COMMIT();
    }

    for (int i = tid; i < KCODES; i += 512) sBk[i] = g_embsq[i];
    if (tid < 128) { sCnt[tid] = 0; sBest[tid] = CUDART_INF_F; }
    if (tid == 0) sOvf[0] = 0;

    // ---- A staging + rowsq; sT aliased into B buffer 1 ----
    float* sT = (float*)(sm + SB_OFF + SB_BUF);
    int b = n0 >> 10, hw0 = n0 & 1023;
    const float* xb = x + (size_t)b * DIM * HW + hw0;
    float rs = 0.f;
    for (int cc0 = 0; cc0 < 8; cc0++) {
        __syncthreads();
#pragma unroll
        for (int i = 0; i < 8; i++) {
            int idx = tid + i * 512, ci = idx >> 7, nn = idx & 127;
            sT[ci * 129 + nn] = xb[(cc0 * 32 + ci) * HW + nn];
        }
        __syncthreads();
#pragma unroll
        for (int i = 0; i < 4; i++) {
            int idx = tid + i * 512, nn = idx >> 4, cp = idx & 15;
            float f0 = sT[(2 * cp) * 129 + nn];
            float f1 = sT[(2 * cp + 1) * 129 + nn];
            __nv_bfloat16 h0 = __float2bfloat16_rn(f0);
            __nv_bfloat16 h1 = __float2bfloat16_rn(f1);
            sA[nn * SA_ST + cc0 * 16 + cp] =
                ((uint32_t)__bfloat16_as_ushort(h1) << 16) | __bfloat16_as_ushort(h0);
        }
        if (tid < 128) {   // exact sequential rowsq
#pragma unroll
            for (int c = 0; c < 32; c++) {
                float v = sT[c * 129 + tid];
                rs = __fadd_rn(rs, __fmul_rn(v, v));
            }
        }
    }
    __syncthreads();
    if (tid < 128) sAn[tid] = rs;

    // panel 1 -> buf1
    {
        const uint32_t* gsrc = g_epack + (size_t)128 * 128;
#pragma unroll
        for (int i = 0; i < 8; i++) {
            int seg = tid + i * 512, code = seg >> 5, j = seg & 31;
            cp16(smu + (uint32_t)(SB_OFF + SB_BUF + code * SA_ST + j * 4) * 4,
                 gsrc + code * 128 + j * 4);
        }
        CP_COMMIT();
    }

    for (int p = 0; p < 8; p++) {
        if (p < 7) CP_WAIT(1); else CP_WAIT(0);
        __syncthreads();
        const uint32_t* Bbuf = sm + SB_OFF + (p & 1) * SB_BUF;

        float acc[2][4][4];
#pragma unroll
        for (int mt = 0; mt < 2; mt++)
#pragma unroll
            for (int nt = 0; nt < 4; nt++)
#pragma unroll
                for (int e2 = 0; e2 < 4; e2++) acc[mt][nt][e2] = 0.f;

        const uint32_t* Ab = sA + (wm * 32 + g) * SA_ST;
        const uint32_t* Bb = Bbuf + (wn * 32 + g) * SA_ST;
#pragma unroll
        for (int ks = 0; ks < 16; ks++) {
            uint32_t a[2][4];
#pragma unroll
            for (int mt = 0; mt < 2; mt++) {
                const uint32_t* ap = Ab + mt * 16 * SA_ST + ks * 8 + tg;
                a[mt][0] = ap[0];
                a[mt][1] = ap[8 * SA_ST];
                a[mt][2] = ap[4];
                a[mt][3] = ap[8 * SA_ST + 4];
            }
#pragma unroll
            for (int nt = 0; nt < 4; nt++) {
                uint32_t b0 = Bb[nt * 8 * SA_ST + ks * 8 + tg];
                uint32_t b1 = Bb[nt * 8 * SA_ST + ks * 8 + tg + 4];
#pragma unroll
                for (int mt = 0; mt < 2; mt++) {
                    asm volatile(
                        "mma.sync.aligned.m16n8k16.row.col.f32.bf16.bf16.f32 "
                        "{%0,%1,%2,%3}, {%4,%5,%6,%7}, {%8,%9}, {%0,%1,%2,%3};"
                        : "+f"(acc[mt][nt][0]), "+f"(acc[mt][nt][1]),
                          "+f"(acc[mt][nt][2]), "+f"(acc[mt][nt][3])
                        : "r"(a[mt][0]), "r"(a[mt][1]), "r"(a[mt][2]), "r"(a[mt][3]),
                          "r"(b0), "r"(b1));
                }
            }
        }

        // ---- phase 1: per-(row,warp) min ----
        int kb = p * 128 + wn * 32 + 2 * tg;
        float bkv[4][2];
#pragma unroll
        for (int nt = 0; nt < 4; nt++) {
            bkv[nt][0] = sBk[kb + nt * 8];
            bkv[nt][1] = sBk[kb + nt * 8 + 1];
        }
        float mn[4] = {CUDART_INF_F, CUDART_INF_F, CUDART_INF_F, CUDART_INF_F};
#pragma unroll
        for (int mt = 0; mt < 2; mt++)
#pragma unroll
            for (int nt = 0; nt < 4; nt++) {
                float t0 = __fmaf_rn(-2.f, acc[mt][nt][0], bkv[nt][0]);
                float t1 = __fmaf_rn(-2.f, acc[mt][nt][1], bkv[nt][1]);
                float t2 = __fmaf_rn(-2.f, acc[mt][nt][2], bkv[nt][0]);
                float t3 = __fmaf_rn(-2.f, acc[mt][nt][3], bkv[nt][1]);
                mn[mt * 2]     = fminf(mn[mt * 2], fminf(t0, t1));
                mn[mt * 2 + 1] = fminf(mn[mt * 2 + 1], fminf(t2, t3));
            }
#pragma unroll
        for (int i = 0; i < 4; i++) {
            mn[i] = fminf(mn[i], __shfl_xor_sync(0xffffffffu, mn[i], 1));
            mn[i] = fminf(mn[i], __shfl_xor_sync(0xffffffffu, mn[i], 2));
        }
        if (tg == 0) {
#pragma unroll
            for (int mt = 0; mt < 2; mt++)
#pragma unroll
                for (int h = 0; h < 2; h++) {
                    int r = wm * 32 + mt * 16 + g + 8 * h;
                    sMnW[r * 4 + wn] = mn[mt * 2 + h];
                }
        }
        __syncthreads();

        // prefetch panel p+2
        if (p + 2 < 8) {
            const uint32_t* gsrc = g_epack + (size_t)(p + 2) * 128 * 128;
            uint32_t dst = smu + (uint32_t)(SB_OFF + (p & 1) * SB_BUF) * 4;
#pragma unroll
            for (int i = 0; i < 8; i++) {
                int seg = tid + i * 512, code = seg >> 5, j = seg & 31;
                cp16(dst + (uint32_t)(code * SA_ST + j * 4) * 4,
                     gsrc + code * 128 + j * 4);
            }
            CP_COMMIT();
        }

        // ---- phase 2: capture candidates vs global running best ----
        float thr[4];
#pragma unroll
        for (int mt = 0; mt < 2; mt++)
#pragma unroll
            for (int h = 0; h < 2; h++) {
                int r = wm * 32 + mt * 16 + g + 8 * h;
                float t4 = fminf(fminf(sMnW[r * 4 + 0], sMnW[r * 4 + 1]),
                                 fminf(sMnW[r * 4 + 2], sMnW[r * 4 + 3]));
                thr[mt * 2 + h] = fminf(sBest[r], t4);
            }
#pragma unroll
        for (int mt = 0; mt < 2; mt++)
#pragma unroll
            for (int nt = 0; nt < 4; nt++)
#pragma unroll
                for (int e2 = 0; e2 < 4; e2++) {
                    float t = __fmaf_rn(-2.f, acc[mt][nt][e2], bkv[nt][e2 & 1]);
                    int h = e2 >> 1;
                    if (t <= thr[mt * 2 + h] + MARGIN) {
                        int r = wm * 32 + mt * 16 + g + 8 * h;
                        int k = kb + nt * 8 + (e2 & 1);
                        int pos = atomicAdd(&sCnt[r], 1);
                        if (pos < CANDCAP) sCand[r * CANDCAP + pos] = (unsigned short)k;
                    }
                }
        __syncthreads();
        if (wn == 0 && tg == 0) {
#pragma unroll
            for (int mt = 0; mt < 2; mt++)
#pragma unroll
                for (int h = 0; h < 2; h++) {
                    int r = wm * 32 + mt * 16 + g + 8 * h;
                    sBest[r] = thr[mt * 2 + h];
                }
        }
    }
    __syncthreads();

    // ---- stage x slice into SMEM (B buffers dead): sX[c*129 + row], f32 ----
    float* sX = (float*)(sm + SB_OFF);   // 256*129 u32 = 33024 <= 33792 available
    for (int i = 0; i < 16; i++) {
        int idx = tid + i * 512;               // 0..8191 per pass? need 32768 total
        // 32768 elements / 512 threads = 64 iters; do 4 elems per iter via separate loop
        (void)idx;
        break;
    }
#pragma unroll 1
    for (int idx = tid; idx < DIM * 128; idx += 512) {
        int c = idx >> 7, nn = idx & 127;
        sX[c * 129 + nn] = xb[c * HW + nn];
    }
    __syncthreads();

    // ---- in-block exact rescore (R4's bit-exact chain), x from SMEM ----
    if (tid < 128) sKey[tid] = 0xFFFFFFFFFFFFFFFFull;
    __syncthreads();

    int rr = tid & 127, slot = tid >> 7;   // 4 slots per row
    int cnt = sCnt[rr];
    if (cnt <= CANDCAP) {
        float an = sAn[rr];
        for (int s = slot; s < cnt; s += 4) {
            int k = sCand[rr * CANDCAP + s];
            const float* ep = e + (size_t)k * DIM;
            float a = 0.f;
#pragma unroll 8
            for (int d = 0; d < DIM; d++)
                a = __fmaf_rn(sX[d * 129 + rr], ep[d], a);
            float sc = __fsub_rn(__fadd_rn(an, sBk[k]), __fmul_rn(2.0f, a));
            atomicMin(&sKey[rr], mkkey(sc, k));
        }
    } else if (slot == 0) {
        int pidx = atomicAdd(&sOvf[0], 1);
        sOvf[1 + pidx] = rr;
    }
    __syncthreads();

    // overflow rows (rare at cap 32): one warp per row, full exact scan from SMEM
    int novf = sOvf[0];
    for (int li = w; li < novf; li += 16) {
        int r2 = sOvf[1 + li];
        float an2 = sAn[r2];
        unsigned long long bk = 0xFFFFFFFFFFFFFFFFull;
        for (int k = lane; k < KCODES; k += 32) {
            const float* ep = e + (size_t)k * DIM;
            float a = 0.f;
#pragma unroll 8
            for (int d = 0; d < DIM; d++)
                a = __fmaf_rn(sX[d * 129 + r2], ep[d], a);
            float sc = __fsub_rn(__fadd_rn(an2, sBk[k]), __fmul_rn(2.0f, a));
            unsigned long long kk = mkkey(sc, k);
            if (kk < bk) bk = kk;
        }
#pragma unroll
        for (int m = 16; m > 0; m >>= 1) {
            unsigned long long o = __shfl_xor_sync(0xffffffffu, bk, m);
            if (o < bk) bk = o;
        }
        if (lane == 0) sKey[r2] = bk;
    }
    __syncthreads();
    if (tid < 128) g_idx[n0 + tid] = (int)(sKey[tid] & 0xFFFFFFFFu);
}

// ---------------- fused outputs: quantized_st + one-hot encodings + loss ----
// 1024 blocks x 256 threads (32 rows per block).
// Phase A (quantized+loss): thread (sub,rowl) — lanes sweep rows -> coalesced.
// Phase B (encodings): warp-per-row — lanes sweep columns -> coalesced.
__global__ __launch_bounds__(256) void k_out(const float* __restrict__ x,
                                             const float* __restrict__ emb,
                                             float* __restrict__ out) {
    int rowl = threadIdx.x & 31, sub = threadIdx.x >> 5;
    int n = blockIdx.x * 32 + rowl;
    int b = n >> 10, hw = n & 1023;
    const float* xp = x + (size_t)b * DIM * HW + hw;
    float* qp = out + 1 + (size_t)b * DIM * HW + hw;
    int idx = g_idx[n];
    const float* ep = emb + (size_t)idx * DIM;
    double ssum = 0.0;
    int c0 = sub * 32;
#pragma unroll 4
    for (int i = 0; i < 32; i++) {
        int c = c0 + i;
        float in = xp[c * HW];
        float q  = ep[c];
        float d  = __fsub_rn(q, in);          // fl(q - in)
        float st = __fadd_rn(in, d);          // fl(in + d)
        qp[c * HW] = st;
        ssum += (double)__fmul_rn(d, d);
    }

    // ---- Phase B: one-hot encodings, warp-per-row coalesced ----
    int lane = rowl;
#pragma unroll
    for (int rr = 0; rr < 4; rr++) {
        int n2 = blockIdx.x * 32 + sub * 4 + rr;
        int idx2 = g_idx[n2];
        float* seg = out + 1 + (size_t)N_TOTAL * DIM + (size_t)n2 * KCODES;
        if (lane < 3) seg[lane] = 0.f;
        if (lane == 3) seg[1023] = 0.f;
        uint4* v4 = (uint4*)(seg + 3);
#pragma unroll
        for (int it = 0; it < 8; it++) {
            int i = it * 32 + lane;
            if (i < 255) v4[i] = make_uint4(0, 0, 0, 0);
        }
        __syncwarp();
        if (lane == 0) seg[idx2] = 1.0f;
    }

    __shared__ double sred[256];
    sred[threadIdx.x] = ssum;
    __syncthreads();
    for (int s = 128; s > 0; s >>= 1) {
        if (threadIdx.x < s) sred[threadIdx.x] += sred[threadIdx.x + s];
        __syncthreads();
    }
    if (threadIdx.x == 0) g_partial[blockIdx.x] = sred[0];
}

__global__ void k_loss(float* __restrict__ out) {
    __shared__ double sred[256];
    double a = 0.0;
#pragma unroll
    for (int i = 0; i < 4; i++) a += g_partial[threadIdx.x * 4 + i];
    sred[threadIdx.x] = a;
    __syncthreads();
    for (int s = 128; s > 0; s >>= 1) {
        if (threadIdx.x < s) sred[threadIdx.x] += sred[threadIdx.x + s];
        __syncthreads();
    }
    if (threadIdx.x == 0) {
        double m = sred[0] / (double)((long long)N_TOTAL * DIM);
        out[0] = (float)(m + 0.25 * m);
    }
}

extern "C" void kernel_launch(void* const* d_in, const int* in_sizes, int n_in,
                              void* d_out, int out_size) {
    const float* x = (const float*)d_in[0];
    const float* e = (const float*)d_in[1];
    if (n_in >= 2 && in_sizes[0] == KCODES * DIM && in_sizes[1] == N_TOTAL * DIM) {
        x = (const float*)d_in[1];
        e = (const float*)d_in[0];
    }
    float* out = (float*)d_out;

    cudaFuncSetAttribute(k_gemm, cudaFuncAttributeMaxDynamicSharedMemorySize, SMEM_BYTES);

    k_prep<<<32, 32>>>(e);
    k_gemm<<<N_TOTAL / 128, 512, SMEM_BYTES>>>(x, e);
    k_out<<<N_TOTAL / 32, 256>>>(x, e, out);
    k_loss<<<1, 256>>>(out);
}